// round 6
// baseline (speedup 1.0000x reference)
#include <cuda_runtime.h>
#include <cuda_bf16.h>
#include <cstdint>

#define MAXN 50000
#define MAXE 600000
#define RNUM 16
#define DIN  64
#define HID  128

// ---------------- scratch ----------------------------------------------------
__device__ float g_msg1[(size_t)MAXE * HID];    // per-edge layer-1 messages (dst-slot order)
__device__ float g_msg2[(size_t)MAXE * DIN];    // per-edge layer-2 messages (dst-slot order)
__device__ __nv_bfloat16 g_embh[(size_t)MAXN * DIN];
__device__ __nv_bfloat16 g_embl[(size_t)MAXN * DIN];
__device__ __nv_bfloat16 g_x1h[(size_t)MAXN * HID];
__device__ __nv_bfloat16 g_x1l[(size_t)MAXN * HID];
__device__ __nv_bfloat16 g_w1h[RNUM * DIN * HID];
__device__ __nv_bfloat16 g_w1l[RNUM * DIN * HID];
__device__ __nv_bfloat16 g_w2h[RNUM * HID * DIN];
__device__ __nv_bfloat16 g_w2l[RNUM * HID * DIN];
__device__ int g_esrc1[MAXE];        // emb row of src, relation-sorted pos
__device__ int g_esrc2[MAXE];        // src node, relation-sorted pos
__device__ int g_slot[MAXE];         // dst-sorted slot for relation-sorted pos
__device__ int g_dcnt[MAXN];         // dst degree histogram
__device__ int g_doff[MAXN + 1];     // dst CSR offsets
__device__ int g_dcur[MAXN];         // dst cursors
__device__ int g_cnt[RNUM];
__device__ int g_off[RNUM + 1];
__device__ int g_cursor[RNUM];
__device__ int g_tileoff[RNUM + 1];

// ---------------- PTX helpers ------------------------------------------------
__device__ __forceinline__ uint32_t smem_u32(const void* p) {
    return (uint32_t)__cvta_generic_to_shared(p);
}
__device__ __forceinline__ void ldsm_x4(uint32_t* r, uint32_t a) {
    asm volatile("ldmatrix.sync.aligned.m8n8.x4.shared.b16 {%0,%1,%2,%3}, [%4];\n"
                 : "=r"(r[0]), "=r"(r[1]), "=r"(r[2]), "=r"(r[3]) : "r"(a));
}
__device__ __forceinline__ void ldsm_x4t(uint32_t* r, uint32_t a) {
    asm volatile("ldmatrix.sync.aligned.m8n8.x4.trans.shared.b16 {%0,%1,%2,%3}, [%4];\n"
                 : "=r"(r[0]), "=r"(r[1]), "=r"(r[2]), "=r"(r[3]) : "r"(a));
}
__device__ __forceinline__ void mma_bf16(float* c, const uint32_t* a, uint32_t b0, uint32_t b1) {
    asm volatile("mma.sync.aligned.m16n8k16.row.col.f32.bf16.bf16.f32 "
                 "{%0,%1,%2,%3},{%4,%5,%6,%7},{%8,%9},{%0,%1,%2,%3};\n"
                 : "+f"(c[0]), "+f"(c[1]), "+f"(c[2]), "+f"(c[3])
                 : "r"(a[0]), "r"(a[1]), "r"(a[2]), "r"(a[3]), "r"(b0), "r"(b1));
}
__device__ __forceinline__ void cpasync16(uint32_t saddr, const void* g) {
    asm volatile("cp.async.cg.shared.global [%0], [%1], 16;\n" :: "r"(saddr), "l"(g));
}
__device__ __forceinline__ void cp_commit() {
    asm volatile("cp.async.commit_group;\n");
}
__device__ __forceinline__ void cp_wait0() {
    asm volatile("cp.async.wait_group 0;\n");
}
__device__ __forceinline__ void split_bf16(float v, __nv_bfloat16& h, __nv_bfloat16& l) {
    h = __float2bfloat16(v);
    l = __float2bfloat16(v - __bfloat162float(h));
}

// ---------------- prep: zero counters + convert weights/emb ------------------
__global__ void k_prep(const float* __restrict__ emb, const float* __restrict__ W1,
                       const float* __restrict__ W2, int N) {
    int stride = gridDim.x * blockDim.x;
    int i = blockIdx.x * blockDim.x + threadIdx.x;
    for (int k = i; k < N; k += stride) g_dcnt[k] = 0;
    int ne = N * DIN;
    for (int k = i; k < ne; k += stride) split_bf16(emb[k], g_embh[k], g_embl[k]);
    for (int k = i; k < RNUM * DIN * HID; k += stride) split_bf16(W1[k], g_w1h[k], g_w1l[k]);
    for (int k = i; k < RNUM * HID * DIN; k += stride) split_bf16(W2[k], g_w2h[k], g_w2l[k]);
    if (blockIdx.x == 0 && threadIdx.x < RNUM) g_cnt[threadIdx.x] = 0;
}

// ---------------- histograms (relation + dst) ---------------------------------
__global__ void k_hist(const int* __restrict__ et, const int* __restrict__ eidx, int E) {
    __shared__ int s[RNUM];
    if (threadIdx.x < RNUM) s[threadIdx.x] = 0;
    __syncthreads();
    int stride = gridDim.x * blockDim.x;
    for (int i = blockIdx.x * blockDim.x + threadIdx.x; i < E; i += stride) {
        atomicAdd(&s[et[i]], 1);
        atomicAdd(&g_dcnt[eidx[E + i]], 1);
    }
    __syncthreads();
    if (threadIdx.x < RNUM && s[threadIdx.x]) atomicAdd(&g_cnt[threadIdx.x], s[threadIdx.x]);
}

// ---------------- relation prefix (tiny) --------------------------------------
__global__ void k_scan() {
    if (threadIdx.x == 0 && blockIdx.x == 0) {
        int o = 0, t = 0;
        for (int r = 0; r < RNUM; ++r) {
            g_off[r] = o; g_cursor[r] = o; g_tileoff[r] = t;
            o += g_cnt[r];
            t += (g_cnt[r] + 255) >> 8;
        }
        g_off[RNUM] = o; g_tileoff[RNUM] = t;
    }
}

// ---------------- dst prefix scan (single block, 1024 thr) --------------------
__global__ void __launch_bounds__(1024) k_dscan(int N, int E) {
    __shared__ int wsum[32];
    __shared__ int carry;
    int t = threadIdx.x, lane = t & 31, w = t >> 5;
    if (t == 0) carry = 0;
    __syncthreads();
    for (int base = 0; base < N; base += 1024) {
        int v = (base + t < N) ? g_dcnt[base + t] : 0;
        int x = v;
        #pragma unroll
        for (int o = 1; o < 32; o <<= 1) {
            int y = __shfl_up_sync(0xffffffffu, x, o);
            if (lane >= o) x += y;
        }
        if (lane == 31) wsum[w] = x;
        __syncthreads();
        if (w == 0) {
            int ws = wsum[lane];
            #pragma unroll
            for (int o = 1; o < 32; o <<= 1) {
                int y = __shfl_up_sync(0xffffffffu, ws, o);
                if (lane >= o) ws += y;
            }
            wsum[lane] = ws;
        }
        __syncthreads();
        int excl = carry + x - v + (w ? wsum[w - 1] : 0);
        if (base + t < N) { g_doff[base + t] = excl; g_dcur[base + t] = excl; }
        int total = wsum[31];
        __syncthreads();
        if (t == 0) carry += total;
        __syncthreads();
    }
    if (t == 0) g_doff[N] = E;
}

// ---------------- bucket: relation-sorted pos + dst-sorted slot ---------------
__global__ void k_bucket(const int* __restrict__ et, const int* __restrict__ eidx,
                         const int* __restrict__ nid, int E) {
    __shared__ int lcnt[RNUM], lbase[RNUM];
    int e = blockIdx.x * 256 + threadIdx.x;
    if (threadIdx.x < RNUM) lcnt[threadIdx.x] = 0;
    __syncthreads();
    int r = 0, rank = 0, s = 0, d = 0;
    if (e < E) {
        r = et[e]; s = eidx[e]; d = eidx[E + e];
        rank = atomicAdd(&lcnt[r], 1);
    }
    __syncthreads();
    if (threadIdx.x < RNUM && lcnt[threadIdx.x])
        lbase[threadIdx.x] = atomicAdd(&g_cursor[threadIdx.x], lcnt[threadIdx.x]);
    __syncthreads();
    if (e < E) {
        int pos = lbase[r] + rank;
        int slot = atomicAdd(&g_dcur[d], 1);
        g_esrc1[pos] = nid[s];
        g_esrc2[pos] = s;
        g_slot[pos]  = slot;
    }
}

// ---------------- layer-1: 256 edges/block, pipelined 64x128x64 sub-tiles ----
#define PA1 72
#define PW1 136
#define SM1_WL   (64 * PW1)
#define SM1_A    (2 * 64 * PW1)
#define SM1_ABUF (2 * 64 * PA1)
#define SMEM1_BYTES ((SM1_A + 2 * SM1_ABUF) * 2)

__global__ void __launch_bounds__(256) k_gemm1() {
    extern __shared__ __nv_bfloat16 sm[];
    __nv_bfloat16* Wh = sm;
    __nv_bfloat16* Wl = sm + SM1_WL;
    __shared__ int sslot[2][64];

    int b = blockIdx.x;
    if (b >= g_tileoff[RNUM]) return;
    int tid = threadIdx.x;
    int r = 0;
    while (g_tileoff[r + 1] <= b) ++r;
    int base = g_off[r] + (b - g_tileoff[r]) * 256;
    int rend = g_off[r + 1];
    int nsub = min(4, (rend - base + 63) >> 6);

    {
        int row = tid >> 2, seg = tid & 3;
        size_t src = ((size_t)r * DIN + row) * HID + seg * 32;
        uint32_t dh = smem_u32(Wh + row * PW1 + seg * 32);
        uint32_t dl = smem_u32(Wl + row * PW1 + seg * 32);
        #pragma unroll
        for (int q = 0; q < 4; ++q) {
            cpasync16(dh + q * 16, g_w1h + src + q * 8);
            cpasync16(dl + q * 16, g_w1l + src + q * 8);
        }
    }

    int e = tid >> 2, p = tid & 3;
    auto prefetch = [&](int ss, int bb) {
        int gi = base + ss * 64 + e;
        int row = 0;
        bool v = gi < rend;
        if (v) row = g_esrc1[gi];
        if (p == 0) sslot[bb][e] = v ? g_slot[gi] : 0;
        const __nv_bfloat16* sh = g_embh + (size_t)row * DIN + p * 16;
        const __nv_bfloat16* sl = g_embl + (size_t)row * DIN + p * 16;
        uint32_t dh = smem_u32(sm + SM1_A + bb * SM1_ABUF + e * PA1 + p * 16);
        uint32_t dl = dh + (64 * PA1) * 2;
        cpasync16(dh, sh); cpasync16(dh + 16, sh + 8);
        cpasync16(dl, sl); cpasync16(dl + 16, sl + 8);
        cp_commit();
    };
    prefetch(0, 0);

    int wid = tid >> 5, lane = tid & 31;
    int wm = wid & 1, wn = wid >> 1;
    int mbase = 32 * wm, nbase = 32 * wn;
    uint32_t aBase = smem_u32(sm + SM1_A) +
        (((mbase + (lane & 15)) * PA1 + 8 * (lane >> 4)) << 1);
    uint32_t bOffH = smem_u32(Wh) +
        (((((lane & 7) + 8 * ((lane >> 3) & 1)) * PW1) + nbase + 8 * (lane >> 4)) << 1);
    uint32_t bOffL = bOffH + (SM1_WL << 1);

    int t = lane & 3;
    bool evenp = (t & 1) == 0;

    for (int s = 0; s < nsub; ++s) {
        cp_wait0();
        __syncthreads();
        if (s + 1 < nsub) prefetch(s + 1, (s + 1) & 1);

        uint32_t aOffH = aBase + (s & 1) * (SM1_ABUF << 1);
        uint32_t aOffL = aOffH + ((64 * PA1) << 1);

        float c[2][4][4];
        #pragma unroll
        for (int mt = 0; mt < 2; ++mt)
            #pragma unroll
            for (int j = 0; j < 4; ++j)
                #pragma unroll
                for (int q = 0; q < 4; ++q) c[mt][j][q] = 0.f;

        #pragma unroll
        for (int ks = 0; ks < 4; ++ks) {
            int kk = ks * 16;
            uint32_t ah[2][4], al[2][4], bh[2][4], bl[2][4];
            #pragma unroll
            for (int mt = 0; mt < 2; ++mt) {
                ldsm_x4(ah[mt], aOffH + ((16 * mt * PA1 + kk) << 1));
                ldsm_x4(al[mt], aOffL + ((16 * mt * PA1 + kk) << 1));
            }
            #pragma unroll
            for (int pp = 0; pp < 2; ++pp) {
                ldsm_x4t(bh[pp], bOffH + ((kk * PW1) << 1) + pp * 32);
                ldsm_x4t(bl[pp], bOffL + ((kk * PW1) << 1) + pp * 32);
            }
            #pragma unroll
            for (int mt = 0; mt < 2; ++mt)
                #pragma unroll
                for (int j = 0; j < 4; ++j) {
                    int pp = j >> 1, w = j & 1;
                    mma_bf16(c[mt][j], ah[mt], bh[pp][2 * w], bh[pp][2 * w + 1]);
                    mma_bf16(c[mt][j], ah[mt], bl[pp][2 * w], bl[pp][2 * w + 1]);
                    mma_bf16(c[mt][j], al[mt], bh[pp][2 * w], bh[pp][2 * w + 1]);
                }
        }

        // plain STG.128 to dst-sorted slot (no atomics)
        int M = min(64, rend - (base + s * 64));
        #pragma unroll
        for (int mt = 0; mt < 2; ++mt) {
            int rowA = mbase + 16 * mt + (lane >> 2);
            int myrow = evenp ? rowA : rowA + 8;
            bool ok = myrow < M;
            float* bp = g_msg1 + (size_t)sslot[s & 1][ok ? myrow : 0] * HID;
            #pragma unroll
            for (int j = 0; j < 4; ++j) {
                float sx = evenp ? c[mt][j][2] : c[mt][j][0];
                float sy = evenp ? c[mt][j][3] : c[mt][j][1];
                float rx = __shfl_xor_sync(0xffffffffu, sx, 1);
                float ry = __shfl_xor_sync(0xffffffffu, sy, 1);
                if (ok) {
                    if (evenp)
                        *(float4*)(bp + nbase + 8 * j + 2 * t) =
                            make_float4(c[mt][j][0], c[mt][j][1], rx, ry);
                    else
                        *(float4*)(bp + nbase + 8 * j + 2 * (t - 1)) =
                            make_float4(rx, ry, c[mt][j][2], c[mt][j][3]);
                }
            }
        }
    }
}

// ---------------- agg1: segment-sum msg1 + LN1 + ReLU -> bf16 hi/lo ----------
__global__ void k_agg1(const float* __restrict__ g, const float* __restrict__ bb, int N) {
    int node = blockIdx.x * 8 + (threadIdx.x >> 5);
    int lane = threadIdx.x & 31;
    if (node >= N) return;
    int s0 = g_doff[node], s1 = g_doff[node + 1];
    float4 a0 = make_float4(0.f, 0.f, 0.f, 0.f);
    float4 a1 = make_float4(0.f, 0.f, 0.f, 0.f);
    int s = s0;
    for (; s + 1 < s1; s += 2) {
        float4 v0 = ((const float4*)(g_msg1 + (size_t)s * HID))[lane];
        float4 v1 = ((const float4*)(g_msg1 + (size_t)(s + 1) * HID))[lane];
        a0.x += v0.x; a0.y += v0.y; a0.z += v0.z; a0.w += v0.w;
        a1.x += v1.x; a1.y += v1.y; a1.z += v1.z; a1.w += v1.w;
    }
    if (s < s1) {
        float4 v0 = ((const float4*)(g_msg1 + (size_t)s * HID))[lane];
        a0.x += v0.x; a0.y += v0.y; a0.z += v0.z; a0.w += v0.w;
    }
    float4 v;
    v.x = a0.x + a1.x; v.y = a0.y + a1.y; v.z = a0.z + a1.z; v.w = a0.w + a1.w;

    float sum = v.x + v.y + v.z + v.w;
    #pragma unroll
    for (int o = 16; o; o >>= 1) sum += __shfl_xor_sync(0xffffffffu, sum, o);
    float mu = sum * (1.f / HID);
    float dx = v.x - mu, dy = v.y - mu, dz = v.z - mu, dw = v.w - mu;
    float q = dx * dx + dy * dy + dz * dz + dw * dw;
    #pragma unroll
    for (int o = 16; o; o >>= 1) q += __shfl_xor_sync(0xffffffffu, q, o);
    float inv = rsqrtf(q * (1.f / HID) + 1e-5f);
    float4 gv = ((const float4*)g)[lane];
    float4 bv = ((const float4*)bb)[lane];
    float o0 = fmaxf(dx * inv * gv.x + bv.x, 0.f);
    float o1 = fmaxf(dy * inv * gv.y + bv.y, 0.f);
    float o2 = fmaxf(dz * inv * gv.z + bv.z, 0.f);
    float o3 = fmaxf(dw * inv * gv.w + bv.w, 0.f);
    __nv_bfloat16 h[4], l[4];
    split_bf16(o0, h[0], l[0]); split_bf16(o1, h[1], l[1]);
    split_bf16(o2, h[2], l[2]); split_bf16(o3, h[3], l[3]);
    ((uint2*)(g_x1h + (size_t)node * HID))[lane] = *(uint2*)h;
    ((uint2*)(g_x1l + (size_t)node * HID))[lane] = *(uint2*)l;
}

// ---------------- layer-2: 256 edges/block, pipelined 64x64x128 sub-tiles ----
#define PA2 136
#define PW2 72
#define SM2_WL   (128 * PW2)
#define SM2_A    (2 * 128 * PW2)
#define SM2_ABUF (2 * 64 * PA2)
#define SMEM2_BYTES ((SM2_A + 2 * SM2_ABUF) * 2)

__global__ void __launch_bounds__(256) k_gemm2() {
    extern __shared__ __nv_bfloat16 sm[];
    __nv_bfloat16* Wh = sm;
    __nv_bfloat16* Wl = sm + SM2_WL;
    __shared__ int sslot[2][64];

    int b = blockIdx.x;
    if (b >= g_tileoff[RNUM]) return;
    int tid = threadIdx.x;
    int r = 0;
    while (g_tileoff[r + 1] <= b) ++r;
    int base = g_off[r] + (b - g_tileoff[r]) * 256;
    int rend = g_off[r + 1];
    int nsub = min(4, (rend - base + 63) >> 6);

    {
        int row = tid >> 1, half = tid & 1;
        size_t src = ((size_t)r * HID + row) * DIN + half * 32;
        uint32_t dh = smem_u32(Wh + row * PW2 + half * 32);
        uint32_t dl = smem_u32(Wl + row * PW2 + half * 32);
        #pragma unroll
        for (int q = 0; q < 4; ++q) {
            cpasync16(dh + q * 16, g_w2h + src + q * 8);
            cpasync16(dl + q * 16, g_w2l + src + q * 8);
        }
    }

    int e = tid >> 2, p = tid & 3;
    auto prefetch = [&](int ss, int bb) {
        int gi = base + ss * 64 + e;
        int row = 0;
        bool v = gi < rend;
        if (v) row = g_esrc2[gi];
        if (p == 0) sslot[bb][e] = v ? g_slot[gi] : 0;
        const __nv_bfloat16* sh = g_x1h + (size_t)row * HID + p * 32;
        const __nv_bfloat16* sl = g_x1l + (size_t)row * HID + p * 32;
        uint32_t dh = smem_u32(sm + SM2_A + bb * SM2_ABUF + e * PA2 + p * 32);
        uint32_t dl = dh + (64 * PA2) * 2;
        #pragma unroll
        for (int q = 0; q < 4; ++q) {
            cpasync16(dh + q * 16, sh + q * 8);
            cpasync16(dl + q * 16, sl + q * 8);
        }
        cp_commit();
    };
    prefetch(0, 0);

    int wid = tid >> 5, lane = tid & 31;
    int wm = wid & 1, wn = wid >> 1;
    int mbase = 32 * wm, nbase = 16 * wn;
    uint32_t aBase = smem_u32(sm + SM2_A) +
        (((mbase + (lane & 15)) * PA2 + 8 * (lane >> 4)) << 1);
    uint32_t bOffH = smem_u32(Wh) +
        (((((lane & 7) + 8 * ((lane >> 3) & 1)) * PW2) + nbase + 8 * (lane >> 4)) << 1);
    uint32_t bOffL = bOffH + (SM2_WL << 1);

    cp_wait0();
    __syncthreads();
    uint32_t wbh[8][4], wbl[8][4];
    #pragma unroll
    for (int ks = 0; ks < 8; ++ks) {
        ldsm_x4t(wbh[ks], bOffH + ((ks * 16 * PW2) << 1));
        ldsm_x4t(wbl[ks], bOffL + ((ks * 16 * PW2) << 1));
    }

    int t = lane & 3;
    bool evenp = (t & 1) == 0;

    for (int s = 0; s < nsub; ++s) {
        if (s > 0) { cp_wait0(); __syncthreads(); }
        if (s + 1 < nsub) prefetch(s + 1, (s + 1) & 1);

        uint32_t aOffH = aBase + (s & 1) * (SM2_ABUF << 1);
        uint32_t aOffL = aOffH + ((64 * PA2) << 1);

        float c[2][2][4];
        #pragma unroll
        for (int mt = 0; mt < 2; ++mt)
            #pragma unroll
            for (int j = 0; j < 2; ++j)
                #pragma unroll
                for (int q = 0; q < 4; ++q) c[mt][j][q] = 0.f;

        #pragma unroll
        for (int ks = 0; ks < 8; ++ks) {
            int kk = ks * 16;
            uint32_t ah[2][4], al[2][4];
            #pragma unroll
            for (int mt = 0; mt < 2; ++mt) {
                ldsm_x4(ah[mt], aOffH + ((16 * mt * PA2 + kk) << 1));
                ldsm_x4(al[mt], aOffL + ((16 * mt * PA2 + kk) << 1));
            }
            #pragma unroll
            for (int mt = 0; mt < 2; ++mt)
                #pragma unroll
                for (int j = 0; j < 2; ++j) {
                    mma_bf16(c[mt][j], ah[mt], wbh[ks][2 * j], wbh[ks][2 * j + 1]);
                    mma_bf16(c[mt][j], ah[mt], wbl[ks][2 * j], wbl[ks][2 * j + 1]);
                    mma_bf16(c[mt][j], al[mt], wbh[ks][2 * j], wbh[ks][2 * j + 1]);
                }
        }

        int M = min(64, rend - (base + s * 64));
        #pragma unroll
        for (int mt = 0; mt < 2; ++mt) {
            int rowA = mbase + 16 * mt + (lane >> 2);
            int myrow = evenp ? rowA : rowA + 8;
            bool ok = myrow < M;
            float* bp = g_msg2 + (size_t)sslot[s & 1][ok ? myrow : 0] * DIN;
            #pragma unroll
            for (int j = 0; j < 2; ++j) {
                float sx = evenp ? c[mt][j][2] : c[mt][j][0];
                float sy = evenp ? c[mt][j][3] : c[mt][j][1];
                float rx = __shfl_xor_sync(0xffffffffu, sx, 1);
                float ry = __shfl_xor_sync(0xffffffffu, sy, 1);
                if (ok) {
                    if (evenp)
                        *(float4*)(bp + nbase + 8 * j + 2 * t) =
                            make_float4(c[mt][j][0], c[mt][j][1], rx, ry);
                    else
                        *(float4*)(bp + nbase + 8 * j + 2 * (t - 1)) =
                            make_float4(rx, ry, c[mt][j][2], c[mt][j][3]);
                }
            }
        }
    }
}

// ---------------- agg2: segment-sum msg2 + LN2 + residual -> out --------------
__global__ void k_agg2(const int* __restrict__ nid, const float* __restrict__ emb,
                       const float* __restrict__ g, const float* __restrict__ bb,
                       float* __restrict__ out, int N) {
    int node = blockIdx.x * 8 + (threadIdx.x >> 5);
    int lane = threadIdx.x & 31;
    if (node >= N) return;
    int s0 = g_doff[node], s1 = g_doff[node + 1];
    float2 a0 = make_float2(0.f, 0.f), a1 = make_float2(0.f, 0.f);
    int s = s0;
    for (; s + 1 < s1; s += 2) {
        float2 v0 = ((const float2*)(g_msg2 + (size_t)s * DIN))[lane];
        float2 v1 = ((const float2*)(g_msg2 + (size_t)(s + 1) * DIN))[lane];
        a0.x += v0.x; a0.y += v0.y;
        a1.x += v1.x; a1.y += v1.y;
    }
    if (s < s1) {
        float2 v0 = ((const float2*)(g_msg2 + (size_t)s * DIN))[lane];
        a0.x += v0.x; a0.y += v0.y;
    }
    float2 v = make_float2(a0.x + a1.x, a0.y + a1.y);

    float sum = v.x + v.y;
    #pragma unroll
    for (int o = 16; o; o >>= 1) sum += __shfl_xor_sync(0xffffffffu, sum, o);
    float mu = sum * (1.f / DIN);
    float dx = v.x - mu, dy = v.y - mu;
    float q = dx * dx + dy * dy;
    #pragma unroll
    for (int o = 16; o; o >>= 1) q += __shfl_xor_sync(0xffffffffu, q, o);
    float inv = rsqrtf(q * (1.f / DIN) + 1e-5f);
    float2 gv = ((const float2*)g)[lane];
    float2 bv = ((const float2*)bb)[lane];
    float2 xr = ((const float2*)(emb + (size_t)nid[node] * DIN))[lane];
    float2 o2;
    o2.x = dx * inv * gv.x + bv.x + xr.x;
    o2.y = dy * inv * gv.y + bv.y + xr.y;
    ((float2*)(out + (size_t)node * DIN))[lane] = o2;
}

// ---------------- launch -----------------------------------------------------
extern "C" void kernel_launch(void* const* d_in, const int* in_sizes, int n_in,
                              void* d_out, int out_size) {
    const int*   nid   = (const int*)d_in[0];
    const int*   eidx  = (const int*)d_in[1];
    const int*   etype = (const int*)d_in[2];
    const float* emb   = (const float*)d_in[3];
    const float* W1    = (const float*)d_in[4];
    const float* W2    = (const float*)d_in[5];
    const float* ln1g  = (const float*)d_in[6];
    const float* ln1b  = (const float*)d_in[7];
    const float* ln2g  = (const float*)d_in[8];
    const float* ln2b  = (const float*)d_in[9];
    float* out = (float*)d_out;

    int N = in_sizes[0];
    int E = in_sizes[2];

    cudaFuncSetAttribute(k_gemm1, cudaFuncAttributeMaxDynamicSharedMemorySize, SMEM1_BYTES);
    cudaFuncSetAttribute(k_gemm2, cudaFuncAttributeMaxDynamicSharedMemorySize, SMEM2_BYTES);

    int blocks = (E + 255) / 256 + RNUM;

    k_prep<<<1024, 256>>>(emb, W1, W2, N);
    k_hist<<<512, 256>>>(etype, eidx, E);
    k_scan<<<1, 32>>>();
    k_dscan<<<1, 1024>>>(N, E);
    k_bucket<<<(E + 255) / 256, 256>>>(etype, eidx, nid, E);
    k_gemm1<<<blocks, 256, SMEM1_BYTES>>>();
    k_agg1<<<(N + 7) / 8, 256>>>(ln1g, ln1b, N);
    k_gemm2<<<blocks, 256, SMEM2_BYTES>>>();
    k_agg2<<<(N + 7) / 8, 256>>>(nid, emb, ln2g, ln2b, out, N);
}

// round 9
// speedup vs baseline: 1.3640x; 1.3640x over previous
#include <cuda_runtime.h>
#include <cuda_bf16.h>
#include <cstdint>

#define MAXN 50000
#define MAXE 600000
#define RNUM 16
#define DIN  64
#define HID  128

// ---------------- scratch ----------------------------------------------------
__device__ float g_x1acc[(size_t)MAXN * HID];
__device__ float g_x2acc[(size_t)MAXN * DIN];
__device__ __nv_bfloat16 g_embh[(size_t)MAXN * DIN];
__device__ __nv_bfloat16 g_embl[(size_t)MAXN * DIN];
__device__ __nv_bfloat16 g_x1h[(size_t)MAXN * HID];
__device__ __nv_bfloat16 g_x1l[(size_t)MAXN * HID];
__device__ __nv_bfloat16 g_w1h[RNUM * DIN * HID];
__device__ __nv_bfloat16 g_w1l[RNUM * DIN * HID];
__device__ __nv_bfloat16 g_w2h[RNUM * HID * DIN];
__device__ __nv_bfloat16 g_w2l[RNUM * HID * DIN];
__device__ int g_esrc1[MAXE];
__device__ int g_esrc2[MAXE];
__device__ int g_edst[MAXE];
__device__ int g_cnt[RNUM];          // zero at load; k_scan consumes AND resets
__device__ int g_off[RNUM + 1];
__device__ int g_cursor[RNUM];
__device__ int g_tileoff[RNUM + 1];

// ---------------- PTX helpers ------------------------------------------------
__device__ __forceinline__ uint32_t smem_u32(const void* p) {
    return (uint32_t)__cvta_generic_to_shared(p);
}
__device__ __forceinline__ void ldsm_x4(uint32_t* r, uint32_t a) {
    asm volatile("ldmatrix.sync.aligned.m8n8.x4.shared.b16 {%0,%1,%2,%3}, [%4];\n"
                 : "=r"(r[0]), "=r"(r[1]), "=r"(r[2]), "=r"(r[3]) : "r"(a));
}
__device__ __forceinline__ void ldsm_x4t(uint32_t* r, uint32_t a) {
    asm volatile("ldmatrix.sync.aligned.m8n8.x4.trans.shared.b16 {%0,%1,%2,%3}, [%4];\n"
                 : "=r"(r[0]), "=r"(r[1]), "=r"(r[2]), "=r"(r[3]) : "r"(a));
}
__device__ __forceinline__ void mma_bf16(float* c, const uint32_t* a, uint32_t b0, uint32_t b1) {
    asm volatile("mma.sync.aligned.m16n8k16.row.col.f32.bf16.bf16.f32 "
                 "{%0,%1,%2,%3},{%4,%5,%6,%7},{%8,%9},{%0,%1,%2,%3};\n"
                 : "+f"(c[0]), "+f"(c[1]), "+f"(c[2]), "+f"(c[3])
                 : "r"(a[0]), "r"(a[1]), "r"(a[2]), "r"(a[3]), "r"(b0), "r"(b1));
}
__device__ __forceinline__ void cpasync16(uint32_t saddr, const void* g) {
    asm volatile("cp.async.cg.shared.global [%0], [%1], 16;\n" :: "r"(saddr), "l"(g));
}
__device__ __forceinline__ void cp_commit() {
    asm volatile("cp.async.commit_group;\n");
}
__device__ __forceinline__ void cp_wait0() {
    asm volatile("cp.async.wait_group 0;\n");
}
__device__ __forceinline__ void red4(float* p, float x, float y, float z, float w) {
    asm volatile("red.global.add.v4.f32 [%0], {%1,%2,%3,%4};\n"
                 :: "l"(p), "f"(x), "f"(y), "f"(z), "f"(w) : "memory");
}
__device__ __forceinline__ void split_bf16(float v, __nv_bfloat16& h, __nv_bfloat16& l) {
    h = __float2bfloat16(v);
    l = __float2bfloat16(v - __bfloat162float(h));
}

// ---------------- prep: zero + convert + relation hist (fused) ---------------
// g_cnt is consumed+reset by k_scan each launch, so accumulation here starts
// from zero every time (zero-initialized at module load for launch 1).
__global__ void k_prep(const float* __restrict__ emb, const float* __restrict__ W1,
                       const float* __restrict__ W2, const int* __restrict__ et,
                       int N, int E) {
    __shared__ int s[RNUM];
    if (threadIdx.x < RNUM) s[threadIdx.x] = 0;
    __syncthreads();
    int stride = gridDim.x * blockDim.x;
    int i = blockIdx.x * blockDim.x + threadIdx.x;
    float4 z = make_float4(0.f, 0.f, 0.f, 0.f);
    int n1 = N * (HID / 4);
    for (int k = i; k < n1; k += stride) ((float4*)g_x1acc)[k] = z;
    int n2 = N * (DIN / 4);
    for (int k = i; k < n2; k += stride) ((float4*)g_x2acc)[k] = z;
    int ne = N * DIN;
    for (int k = i; k < ne; k += stride) split_bf16(emb[k], g_embh[k], g_embl[k]);
    for (int k = i; k < RNUM * DIN * HID; k += stride) split_bf16(W1[k], g_w1h[k], g_w1l[k]);
    for (int k = i; k < RNUM * HID * DIN; k += stride) split_bf16(W2[k], g_w2h[k], g_w2l[k]);
    for (int k = i; k < E; k += stride) atomicAdd(&s[et[k]], 1);
    __syncthreads();
    if (threadIdx.x < RNUM && s[threadIdx.x]) atomicAdd(&g_cnt[threadIdx.x], s[threadIdx.x]);
}

// ---------------- scan (consume + reset g_cnt) --------------------------------
__global__ void k_scan() {
    if (threadIdx.x == 0 && blockIdx.x == 0) {
        int o = 0, t = 0;
        for (int r = 0; r < RNUM; ++r) {
            g_off[r] = o; g_cursor[r] = o; g_tileoff[r] = t;
            o += g_cnt[r];
            t += (g_cnt[r] + 511) >> 9;        // 512-edge blocks
            g_cnt[r] = 0;                      // reset for next launch
        }
        g_off[RNUM] = o; g_tileoff[RNUM] = t;
    }
}
__global__ void k_bucket(const int* __restrict__ et, const int* __restrict__ eidx,
                         const int* __restrict__ nid, int E) {
    __shared__ int lcnt[RNUM], lbase[RNUM];
    int e = blockIdx.x * 256 + threadIdx.x;
    if (threadIdx.x < RNUM) lcnt[threadIdx.x] = 0;
    __syncthreads();
    int r = 0, rank = 0, s = 0, d = 0;
    if (e < E) {
        r = et[e]; s = eidx[e]; d = eidx[E + e];
        rank = atomicAdd(&lcnt[r], 1);
    }
    __syncthreads();
    if (threadIdx.x < RNUM && lcnt[threadIdx.x])
        lbase[threadIdx.x] = atomicAdd(&g_cursor[threadIdx.x], lcnt[threadIdx.x]);
    __syncthreads();
    if (e < E) {
        int pos = lbase[r] + rank;
        g_esrc1[pos] = nid[s];
        g_esrc2[pos] = s;
        g_edst[pos]  = d;
    }
}

// ---------------- layer-1: 512 edges/block, pipelined 64x128x64 sub-tiles ----
#define PA1 72
#define PW1 136
#define SM1_WL   (64 * PW1)
#define SM1_A    (2 * 64 * PW1)
#define SM1_ABUF (2 * 64 * PA1)
#define SMEM1_BYTES ((SM1_A + 2 * SM1_ABUF) * 2)

__global__ void __launch_bounds__(256) k_gemm1() {
    extern __shared__ __nv_bfloat16 sm[];
    __nv_bfloat16* Wh = sm;
    __nv_bfloat16* Wl = sm + SM1_WL;
    __shared__ int sdst[2][64];

    int b = blockIdx.x;
    if (b >= g_tileoff[RNUM]) return;
    int tid = threadIdx.x;
    int r = 0;
    while (g_tileoff[r + 1] <= b) ++r;
    int base = g_off[r] + (b - g_tileoff[r]) * 512;
    int rend = g_off[r + 1];
    int nsub = min(8, (rend - base + 63) >> 6);

    // stage W1[r] (committed with sub-tile 0's group)
    {
        int row = tid >> 2, seg = tid & 3;
        size_t src = ((size_t)r * DIN + row) * HID + seg * 32;
        uint32_t dh = smem_u32(Wh + row * PW1 + seg * 32);
        uint32_t dl = smem_u32(Wl + row * PW1 + seg * 32);
        #pragma unroll
        for (int q = 0; q < 4; ++q) {
            cpasync16(dh + q * 16, g_w1h + src + q * 8);
            cpasync16(dl + q * 16, g_w1l + src + q * 8);
        }
    }

    int e = tid >> 2, p = tid & 3;
    auto prefetch = [&](int ss, int bb) {
        int gi = base + ss * 64 + e;
        int row = 0;
        bool v = gi < rend;
        if (v) row = g_esrc1[gi];
        if (p == 0) sdst[bb][e] = v ? g_edst[gi] : 0;
        const __nv_bfloat16* sh = g_embh + (size_t)row * DIN + p * 16;
        const __nv_bfloat16* sl = g_embl + (size_t)row * DIN + p * 16;
        uint32_t dh = smem_u32(sm + SM1_A + bb * SM1_ABUF + e * PA1 + p * 16);
        uint32_t dl = dh + (64 * PA1) * 2;
        cpasync16(dh, sh); cpasync16(dh + 16, sh + 8);
        cpasync16(dl, sl); cpasync16(dl + 16, sl + 8);
        cp_commit();
    };
    prefetch(0, 0);

    int wid = tid >> 5, lane = tid & 31;
    int wm = wid & 1, wn = wid >> 1;
    int mbase = 32 * wm, nbase = 32 * wn;
    uint32_t aBase = smem_u32(sm + SM1_A) +
        (((mbase + (lane & 15)) * PA1 + 8 * (lane >> 4)) << 1);
    uint32_t bOffH = smem_u32(Wh) +
        (((((lane & 7) + 8 * ((lane >> 3) & 1)) * PW1) + nbase + 8 * (lane >> 4)) << 1);
    uint32_t bOffL = bOffH + (SM1_WL << 1);

    int t = lane & 3;
    bool evenp = (t & 1) == 0;

    for (int s = 0; s < nsub; ++s) {
        cp_wait0();
        __syncthreads();
        if (s + 1 < nsub) prefetch(s + 1, (s + 1) & 1);

        uint32_t aOffH = aBase + (s & 1) * (SM1_ABUF << 1);
        uint32_t aOffL = aOffH + ((64 * PA1) << 1);

        float c[2][4][4];
        #pragma unroll
        for (int mt = 0; mt < 2; ++mt)
            #pragma unroll
            for (int j = 0; j < 4; ++j)
                #pragma unroll
                for (int q = 0; q < 4; ++q) c[mt][j][q] = 0.f;

        #pragma unroll
        for (int ks = 0; ks < 4; ++ks) {
            int kk = ks * 16;
            uint32_t ah[2][4], al[2][4], bh[2][4], bl[2][4];
            #pragma unroll
            for (int mt = 0; mt < 2; ++mt) {
                ldsm_x4(ah[mt], aOffH + ((16 * mt * PA1 + kk) << 1));
                ldsm_x4(al[mt], aOffL + ((16 * mt * PA1 + kk) << 1));
            }
            #pragma unroll
            for (int pp = 0; pp < 2; ++pp) {
                ldsm_x4t(bh[pp], bOffH + ((kk * PW1) << 1) + pp * 32);
                ldsm_x4t(bl[pp], bOffL + ((kk * PW1) << 1) + pp * 32);
            }
            #pragma unroll
            for (int mt = 0; mt < 2; ++mt)
                #pragma unroll
                for (int j = 0; j < 4; ++j) {
                    int pp = j >> 1, w = j & 1;
                    mma_bf16(c[mt][j], ah[mt], bh[pp][2 * w], bh[pp][2 * w + 1]);
                    mma_bf16(c[mt][j], ah[mt], bl[pp][2 * w], bl[pp][2 * w + 1]);
                    mma_bf16(c[mt][j], al[mt], bh[pp][2 * w], bh[pp][2 * w + 1]);
                }
        }

        int M = min(64, rend - (base + s * 64));
        #pragma unroll
        for (int mt = 0; mt < 2; ++mt) {
            int rowA = mbase + 16 * mt + (lane >> 2);
            int myrow = evenp ? rowA : rowA + 8;
            bool ok = myrow < M;
            float* bp = g_x1acc + (size_t)sdst[s & 1][ok ? myrow : 0] * HID;
            #pragma unroll
            for (int j = 0; j < 4; ++j) {
                float sx = evenp ? c[mt][j][2] : c[mt][j][0];
                float sy = evenp ? c[mt][j][3] : c[mt][j][1];
                float rx = __shfl_xor_sync(0xffffffffu, sx, 1);
                float ry = __shfl_xor_sync(0xffffffffu, sy, 1);
                if (ok) {
                    if (evenp)
                        red4(bp + nbase + 8 * j + 2 * t,
                             c[mt][j][0], c[mt][j][1], rx, ry);
                    else
                        red4(bp + nbase + 8 * j + 2 * (t - 1),
                             rx, ry, c[mt][j][2], c[mt][j][3]);
                }
            }
        }
    }
}

// ---------------- LN1 + ReLU -> bf16 hi/lo -----------------------------------
__global__ void k_ln1(const float* __restrict__ g, const float* __restrict__ bb, int N) {
    int w = (blockIdx.x * blockDim.x + threadIdx.x) >> 5;
    int lane = threadIdx.x & 31;
    if (w >= N) return;
    float4 v = ((const float4*)(g_x1acc + (size_t)w * HID))[lane];
    float s = v.x + v.y + v.z + v.w;
    #pragma unroll
    for (int o = 16; o; o >>= 1) s += __shfl_xor_sync(0xffffffffu, s, o);
    float mu = s * (1.f / HID);
    float dx = v.x - mu, dy = v.y - mu, dz = v.z - mu, dw = v.w - mu;
    float q = dx * dx + dy * dy + dz * dz + dw * dw;
    #pragma unroll
    for (int o = 16; o; o >>= 1) q += __shfl_xor_sync(0xffffffffu, q, o);
    float inv = rsqrtf(q * (1.f / HID) + 1e-5f);
    float4 gv = ((const float4*)g)[lane];
    float4 bv = ((const float4*)bb)[lane];
    float o0 = fmaxf(dx * inv * gv.x + bv.x, 0.f);
    float o1 = fmaxf(dy * inv * gv.y + bv.y, 0.f);
    float o2 = fmaxf(dz * inv * gv.z + bv.z, 0.f);
    float o3 = fmaxf(dw * inv * gv.w + bv.w, 0.f);
    __nv_bfloat16 h[4], l[4];
    split_bf16(o0, h[0], l[0]); split_bf16(o1, h[1], l[1]);
    split_bf16(o2, h[2], l[2]); split_bf16(o3, h[3], l[3]);
    ((uint2*)(g_x1h + (size_t)w * HID))[lane] = *(uint2*)h;
    ((uint2*)(g_x1l + (size_t)w * HID))[lane] = *(uint2*)l;
}

// ---------------- layer-2: 512 edges/block, pipelined 64x64x128 sub-tiles ----
#define PA2 136
#define PW2 72
#define SM2_WL   (128 * PW2)
#define SM2_A    (2 * 128 * PW2)
#define SM2_ABUF (2 * 64 * PA2)
#define SMEM2_BYTES ((SM2_A + 2 * SM2_ABUF) * 2)

__global__ void __launch_bounds__(256) k_gemm2() {
    extern __shared__ __nv_bfloat16 sm[];
    __nv_bfloat16* Wh = sm;
    __nv_bfloat16* Wl = sm + SM2_WL;
    __shared__ int sdst[2][64];

    int b = blockIdx.x;
    if (b >= g_tileoff[RNUM]) return;
    int tid = threadIdx.x;
    int r = 0;
    while (g_tileoff[r + 1] <= b) ++r;
    int base = g_off[r] + (b - g_tileoff[r]) * 512;
    int rend = g_off[r + 1];
    int nsub = min(8, (rend - base + 63) >> 6);

    {
        int row = tid >> 1, half = tid & 1;
        size_t src = ((size_t)r * HID + row) * DIN + half * 32;
        uint32_t dh = smem_u32(Wh + row * PW2 + half * 32);
        uint32_t dl = smem_u32(Wl + row * PW2 + half * 32);
        #pragma unroll
        for (int q = 0; q < 4; ++q) {
            cpasync16(dh + q * 16, g_w2h + src + q * 8);
            cpasync16(dl + q * 16, g_w2l + src + q * 8);
        }
    }

    int e = tid >> 2, p = tid & 3;
    auto prefetch = [&](int ss, int bb) {
        int gi = base + ss * 64 + e;
        int row = 0;
        bool v = gi < rend;
        if (v) row = g_esrc2[gi];
        if (p == 0) sdst[bb][e] = v ? g_edst[gi] : 0;
        const __nv_bfloat16* sh = g_x1h + (size_t)row * HID + p * 32;
        const __nv_bfloat16* sl = g_x1l + (size_t)row * HID + p * 32;
        uint32_t dh = smem_u32(sm + SM2_A + bb * SM2_ABUF + e * PA2 + p * 32);
        uint32_t dl = dh + (64 * PA2) * 2;
        #pragma unroll
        for (int q = 0; q < 4; ++q) {
            cpasync16(dh + q * 16, sh + q * 8);
            cpasync16(dl + q * 16, sl + q * 8);
        }
        cp_commit();
    };
    prefetch(0, 0);

    int wid = tid >> 5, lane = tid & 31;
    int wm = wid & 1, wn = wid >> 1;
    int mbase = 32 * wm, nbase = 16 * wn;
    uint32_t aBase = smem_u32(sm + SM2_A) +
        (((mbase + (lane & 15)) * PA2 + 8 * (lane >> 4)) << 1);
    uint32_t bOffH = smem_u32(Wh) +
        (((((lane & 7) + 8 * ((lane >> 3) & 1)) * PW2) + nbase + 8 * (lane >> 4)) << 1);
    uint32_t bOffL = bOffH + (SM2_WL << 1);

    cp_wait0();
    __syncthreads();
    uint32_t wbh[8][4], wbl[8][4];
    #pragma unroll
    for (int ks = 0; ks < 8; ++ks) {
        ldsm_x4t(wbh[ks], bOffH + ((ks * 16 * PW2) << 1));
        ldsm_x4t(wbl[ks], bOffL + ((ks * 16 * PW2) << 1));
    }

    int t = lane & 3;
    bool evenp = (t & 1) == 0;

    for (int s = 0; s < nsub; ++s) {
        if (s > 0) { cp_wait0(); __syncthreads(); }
        if (s + 1 < nsub) prefetch(s + 1, (s + 1) & 1);

        uint32_t aOffH = aBase + (s & 1) * (SM2_ABUF << 1);
        uint32_t aOffL = aOffH + ((64 * PA2) << 1);

        float c[2][2][4];
        #pragma unroll
        for (int mt = 0; mt < 2; ++mt)
            #pragma unroll
            for (int j = 0; j < 2; ++j)
                #pragma unroll
                for (int q = 0; q < 4; ++q) c[mt][j][q] = 0.f;

        #pragma unroll
        for (int ks = 0; ks < 8; ++ks) {
            int kk = ks * 16;
            uint32_t ah[2][4], al[2][4];
            #pragma unroll
            for (int mt = 0; mt < 2; ++mt) {
                ldsm_x4(ah[mt], aOffH + ((16 * mt * PA2 + kk) << 1));
                ldsm_x4(al[mt], aOffL + ((16 * mt * PA2 + kk) << 1));
            }
            #pragma unroll
            for (int mt = 0; mt < 2; ++mt)
                #pragma unroll
                for (int j = 0; j < 2; ++j) {
                    mma_bf16(c[mt][j], ah[mt], wbh[ks][2 * j], wbh[ks][2 * j + 1]);
                    mma_bf16(c[mt][j], ah[mt], wbl[ks][2 * j], wbl[ks][2 * j + 1]);
                    mma_bf16(c[mt][j], al[mt], wbh[ks][2 * j], wbh[ks][2 * j + 1]);
                }
        }

        int M = min(64, rend - (base + s * 64));
        #pragma unroll
        for (int mt = 0; mt < 2; ++mt) {
            int rowA = mbase + 16 * mt + (lane >> 2);
            int myrow = evenp ? rowA : rowA + 8;
            bool ok = myrow < M;
            float* bp = g_x2acc + (size_t)sdst[s & 1][ok ? myrow : 0] * DIN;
            #pragma unroll
            for (int j = 0; j < 2; ++j) {
                float sx = evenp ? c[mt][j][2] : c[mt][j][0];
                float sy = evenp ? c[mt][j][3] : c[mt][j][1];
                float rx = __shfl_xor_sync(0xffffffffu, sx, 1);
                float ry = __shfl_xor_sync(0xffffffffu, sy, 1);
                if (ok) {
                    if (evenp)
                        red4(bp + nbase + 8 * j + 2 * t,
                             c[mt][j][0], c[mt][j][1], rx, ry);
                    else
                        red4(bp + nbase + 8 * j + 2 * (t - 1),
                             rx, ry, c[mt][j][2], c[mt][j][3]);
                }
            }
        }
    }
}

// ---------------- LN2 + residual ---------------------------------------------
__global__ void k_ln2res(const int* __restrict__ nid, const float* __restrict__ emb,
                         const float* __restrict__ g, const float* __restrict__ bb,
                         float* __restrict__ out, int N) {
    int w = (blockIdx.x * blockDim.x + threadIdx.x) >> 5;
    int lane = threadIdx.x & 31;
    if (w >= N) return;
    float2 v = ((const float2*)(g_x2acc + (size_t)w * DIN))[lane];
    float s = v.x + v.y;
    #pragma unroll
    for (int o = 16; o; o >>= 1) s += __shfl_xor_sync(0xffffffffu, s, o);
    float mu = s * (1.f / DIN);
    float dx = v.x - mu, dy = v.y - mu;
    float q = dx * dx + dy * dy;
    #pragma unroll
    for (int o = 16; o; o >>= 1) q += __shfl_xor_sync(0xffffffffu, q, o);
    float inv = rsqrtf(q * (1.f / DIN) + 1e-5f);
    float2 gv = ((const float2*)g)[lane];
    float2 bv = ((const float2*)bb)[lane];
    float2 xr = ((const float2*)(emb + (size_t)nid[w] * DIN))[lane];
    float2 o2;
    o2.x = dx * inv * gv.x + bv.x + xr.x;
    o2.y = dy * inv * gv.y + bv.y + xr.y;
    ((float2*)(out + (size_t)w * DIN))[lane] = o2;
}

// ---------------- launch -----------------------------------------------------
extern "C" void kernel_launch(void* const* d_in, const int* in_sizes, int n_in,
                              void* d_out, int out_size) {
    const int*   nid   = (const int*)d_in[0];
    const int*   eidx  = (const int*)d_in[1];
    const int*   etype = (const int*)d_in[2];
    const float* emb   = (const float*)d_in[3];
    const float* W1    = (const float*)d_in[4];
    const float* W2    = (const float*)d_in[5];
    const float* ln1g  = (const float*)d_in[6];
    const float* ln1b  = (const float*)d_in[7];
    const float* ln2g  = (const float*)d_in[8];
    const float* ln2b  = (const float*)d_in[9];
    float* out = (float*)d_out;

    int N = in_sizes[0];
    int E = in_sizes[2];

    cudaFuncSetAttribute(k_gemm1, cudaFuncAttributeMaxDynamicSharedMemorySize, SMEM1_BYTES);
    cudaFuncSetAttribute(k_gemm2, cudaFuncAttributeMaxDynamicSharedMemorySize, SMEM2_BYTES);

    int blocks = (E + 511) / 512 + RNUM;

    k_prep<<<1024, 256>>>(emb, W1, W2, etype, N, E);
    k_scan<<<1, 32>>>();
    k_bucket<<<(E + 255) / 256, 256>>>(etype, eidx, nid, E);
    k_gemm1<<<blocks, 256, SMEM1_BYTES>>>();
    k_ln1<<<(N * 32 + 255) / 256, 256>>>(ln1g, ln1b, N);
    k_gemm2<<<blocks, 256, SMEM2_BYTES>>>();
    k_ln2res<<<(N * 32 + 255) / 256, 256>>>(nid, emb, ln2g, ln2b, out, N);
}

// round 11
// speedup vs baseline: 1.4063x; 1.0311x over previous
#include <cuda_runtime.h>
#include <cuda_bf16.h>
#include <cstdint>

#define MAXN 50000
#define MAXE 600000
#define RNUM 16
#define DIN  64
#define HID  128

// ---------------- scratch ----------------------------------------------------
__device__ float g_x1acc[(size_t)MAXN * HID];
__device__ float g_x2acc[(size_t)MAXN * DIN];
__device__ __nv_bfloat16 g_embh[(size_t)MAXN * DIN];
__device__ __nv_bfloat16 g_embl[(size_t)MAXN * DIN];
__device__ __nv_bfloat16 g_x1h[(size_t)MAXN * HID];
__device__ __nv_bfloat16 g_x1l[(size_t)MAXN * HID];
__device__ __nv_bfloat16 g_w1h[RNUM * DIN * HID];
__device__ __nv_bfloat16 g_w1l[RNUM * DIN * HID];
__device__ __nv_bfloat16 g_w2h[RNUM * HID * DIN];
__device__ __nv_bfloat16 g_w2l[RNUM * HID * DIN];
__device__ int g_esrc1[MAXE];
__device__ int g_esrc2[MAXE];
__device__ int g_edst[MAXE];
__device__ int g_cnt[RNUM];          // zero at load; k_scan consumes AND resets
__device__ int g_off[RNUM + 1];
__device__ int g_cursor[RNUM];
__device__ int g_tileoff[RNUM + 1];

// ---------------- PTX helpers ------------------------------------------------
__device__ __forceinline__ uint32_t smem_u32(const void* p) {
    return (uint32_t)__cvta_generic_to_shared(p);
}
__device__ __forceinline__ void ldsm_x4(uint32_t* r, uint32_t a) {
    asm volatile("ldmatrix.sync.aligned.m8n8.x4.shared.b16 {%0,%1,%2,%3}, [%4];\n"
                 : "=r"(r[0]), "=r"(r[1]), "=r"(r[2]), "=r"(r[3]) : "r"(a));
}
__device__ __forceinline__ void ldsm_x4t(uint32_t* r, uint32_t a) {
    asm volatile("ldmatrix.sync.aligned.m8n8.x4.trans.shared.b16 {%0,%1,%2,%3}, [%4];\n"
                 : "=r"(r[0]), "=r"(r[1]), "=r"(r[2]), "=r"(r[3]) : "r"(a));
}
__device__ __forceinline__ void mma_bf16(float* c, const uint32_t* a, uint32_t b0, uint32_t b1) {
    asm volatile("mma.sync.aligned.m16n8k16.row.col.f32.bf16.bf16.f32 "
                 "{%0,%1,%2,%3},{%4,%5,%6,%7},{%8,%9},{%0,%1,%2,%3};\n"
                 : "+f"(c[0]), "+f"(c[1]), "+f"(c[2]), "+f"(c[3])
                 : "r"(a[0]), "r"(a[1]), "r"(a[2]), "r"(a[3]), "r"(b0), "r"(b1));
}
__device__ __forceinline__ void cpasync16(uint32_t saddr, const void* g) {
    asm volatile("cp.async.cg.shared.global [%0], [%1], 16;\n" :: "r"(saddr), "l"(g));
}
__device__ __forceinline__ void cp_commit() {
    asm volatile("cp.async.commit_group;\n");
}
__device__ __forceinline__ void cp_wait0() {
    asm volatile("cp.async.wait_group 0;\n");
}
__device__ __forceinline__ void bar_sync(int id, int n) {
    asm volatile("bar.sync %0, %1;\n" :: "r"(id), "r"(n) : "memory");
}
__device__ __forceinline__ void red4(float* p, float x, float y, float z, float w) {
    asm volatile("red.global.add.v4.f32 [%0], {%1,%2,%3,%4};\n"
                 :: "l"(p), "f"(x), "f"(y), "f"(z), "f"(w) : "memory");
}
__device__ __forceinline__ void split_bf16(float v, __nv_bfloat16& h, __nv_bfloat16& l) {
    h = __float2bfloat16(v);
    l = __float2bfloat16(v - __bfloat162float(h));
}

// ---------------- prep: zero + convert + relation hist (fused) ---------------
__global__ void k_prep(const float* __restrict__ emb, const float* __restrict__ W1,
                       const float* __restrict__ W2, const int* __restrict__ et,
                       int N, int E) {
    __shared__ int s[RNUM];
    if (threadIdx.x < RNUM) s[threadIdx.x] = 0;
    __syncthreads();
    int stride = gridDim.x * blockDim.x;
    int i = blockIdx.x * blockDim.x + threadIdx.x;
    float4 z = make_float4(0.f, 0.f, 0.f, 0.f);
    int n1 = N * (HID / 4);
    for (int k = i; k < n1; k += stride) ((float4*)g_x1acc)[k] = z;
    int n2 = N * (DIN / 4);
    for (int k = i; k < n2; k += stride) ((float4*)g_x2acc)[k] = z;
    int ne = N * DIN;
    for (int k = i; k < ne; k += stride) split_bf16(emb[k], g_embh[k], g_embl[k]);
    for (int k = i; k < RNUM * DIN * HID; k += stride) split_bf16(W1[k], g_w1h[k], g_w1l[k]);
    for (int k = i; k < RNUM * HID * DIN; k += stride) split_bf16(W2[k], g_w2h[k], g_w2l[k]);
    for (int k = i; k < E; k += stride) atomicAdd(&s[et[k]], 1);
    __syncthreads();
    if (threadIdx.x < RNUM && s[threadIdx.x]) atomicAdd(&g_cnt[threadIdx.x], s[threadIdx.x]);
}

// ---------------- scan (consume + reset g_cnt) --------------------------------
__global__ void k_scan() {
    if (threadIdx.x == 0 && blockIdx.x == 0) {
        int o = 0, t = 0;
        for (int r = 0; r < RNUM; ++r) {
            g_off[r] = o; g_cursor[r] = o; g_tileoff[r] = t;
            o += g_cnt[r];
            t += (g_cnt[r] + 511) >> 9;        // 512-edge blocks
            g_cnt[r] = 0;                      // reset for next launch
        }
        g_off[RNUM] = o; g_tileoff[RNUM] = t;
    }
}
__global__ void k_bucket(const int* __restrict__ et, const int* __restrict__ eidx,
                         const int* __restrict__ nid, int E) {
    __shared__ int lcnt[RNUM], lbase[RNUM];
    int e = blockIdx.x * 256 + threadIdx.x;
    if (threadIdx.x < RNUM) lcnt[threadIdx.x] = 0;
    __syncthreads();
    int r = 0, rank = 0, s = 0, d = 0;
    if (e < E) {
        r = et[e]; s = eidx[e]; d = eidx[E + e];
        rank = atomicAdd(&lcnt[r], 1);
    }
    __syncthreads();
    if (threadIdx.x < RNUM && lcnt[threadIdx.x])
        lbase[threadIdx.x] = atomicAdd(&g_cursor[threadIdx.x], lcnt[threadIdx.x]);
    __syncthreads();
    if (e < E) {
        int pos = lbase[r] + rank;
        g_esrc1[pos] = nid[s];
        g_esrc2[pos] = s;
        g_edst[pos]  = d;
    }
}

// ---------------- layer-1: 512 edges/block, 2 groups x 32-edge sub-tiles -----
#define PA1 72
#define PW1 136
#define GE1 32
#define SM1_WL   (64 * PW1)
#define SM1_A    (2 * 64 * PW1)
#define ABUF1    (2 * GE1 * PA1)            // hi+lo elems per 32-edge buffer
#define SMEM1_BYTES ((SM1_A + 4 * ABUF1) * 2)

__global__ void __launch_bounds__(256) k_gemm1() {
    extern __shared__ __nv_bfloat16 sm[];
    __nv_bfloat16* Wh = sm;
    __nv_bfloat16* Wl = sm + SM1_WL;
    __shared__ int sdst[2][2][GE1];

    int b = blockIdx.x;
    if (b >= g_tileoff[RNUM]) return;
    int tid = threadIdx.x;
    int r = 0;
    while (g_tileoff[r + 1] <= b) ++r;
    int base = g_off[r] + (b - g_tileoff[r]) * 512;
    int rend = g_off[r + 1];

    // stage W1[r] (commit bundled with first prefetch)
    {
        int row = tid >> 2, seg = tid & 3;
        size_t src = ((size_t)r * DIN + row) * HID + seg * 32;
        uint32_t dh = smem_u32(Wh + row * PW1 + seg * 32);
        uint32_t dl = smem_u32(Wl + row * PW1 + seg * 32);
        #pragma unroll
        for (int q = 0; q < 4; ++q) {
            cpasync16(dh + q * 16, g_w1h + src + q * 8);
            cpasync16(dl + q * 16, g_w1l + src + q * 8);
        }
    }

    int grp = tid >> 7, gtid = tid & 127;
    int gbase = base + grp * 256;
    int nsub = (rend - gbase + 31) >> 5;
    if (nsub > 8) nsub = 8;
    if (nsub < 0) nsub = 0;

    int e = gtid >> 2, p = gtid & 3;
    auto prefetch = [&](int ss, int bb) {
        int gi = gbase + ss * GE1 + e;
        int row = 0;
        bool v = gi < rend;
        if (v) row = g_esrc1[gi];
        if (p == 0) sdst[grp][bb][e] = v ? g_edst[gi] : 0;
        const __nv_bfloat16* sh = g_embh + (size_t)row * DIN + p * 16;
        const __nv_bfloat16* sl = g_embl + (size_t)row * DIN + p * 16;
        uint32_t dh = smem_u32(sm + SM1_A + (grp * 2 + bb) * ABUF1 + e * PA1 + p * 16);
        uint32_t dl = dh + (GE1 * PA1) * 2;
        cpasync16(dh, sh); cpasync16(dh + 16, sh + 8);
        cpasync16(dl, sl); cpasync16(dl + 16, sl + 8);
        cp_commit();
    };
    prefetch(0, 0);      // commits W + first A tile

    // W staged by ALL 256 threads but read by both groups: one block-wide
    // barrier after everyone's own cp.async drained, then groups go independent.
    cp_wait0();
    __syncthreads();

    int wid = gtid >> 5, lane = gtid & 31;     // wid 0..3 within group
    int nbase = 32 * wid;
    uint32_t aBase = smem_u32(sm + SM1_A + grp * 2 * ABUF1) +
        (((lane & 15) * PA1 + 8 * (lane >> 4)) << 1);
    uint32_t bOffH = smem_u32(Wh) +
        (((((lane & 7) + 8 * ((lane >> 3) & 1)) * PW1) + nbase + 8 * (lane >> 4)) << 1);
    uint32_t bOffL = bOffH + (SM1_WL << 1);

    int t = lane & 3;
    bool evenp = (t & 1) == 0;
    int barid = grp + 1;

    for (int s = 0; s < nsub; ++s) {
        if (s > 0) { cp_wait0(); bar_sync(barid, 128); }
        if (s + 1 < nsub) prefetch(s + 1, (s + 1) & 1);

        uint32_t aOffH = aBase + ((s & 1) * ABUF1 << 1);
        uint32_t aOffL = aOffH + ((GE1 * PA1) << 1);

        float c[2][4][4];
        #pragma unroll
        for (int mt = 0; mt < 2; ++mt)
            #pragma unroll
            for (int j = 0; j < 4; ++j)
                #pragma unroll
                for (int q = 0; q < 4; ++q) c[mt][j][q] = 0.f;

        #pragma unroll
        for (int ks = 0; ks < 4; ++ks) {
            int kk = ks * 16;
            uint32_t ah[2][4], al[2][4], bh[2][4], bl[2][4];
            #pragma unroll
            for (int mt = 0; mt < 2; ++mt) {
                ldsm_x4(ah[mt], aOffH + ((16 * mt * PA1 + kk) << 1));
                ldsm_x4(al[mt], aOffL + ((16 * mt * PA1 + kk) << 1));
            }
            #pragma unroll
            for (int pp = 0; pp < 2; ++pp) {
                ldsm_x4t(bh[pp], bOffH + ((kk * PW1) << 1) + pp * 32);
                ldsm_x4t(bl[pp], bOffL + ((kk * PW1) << 1) + pp * 32);
            }
            #pragma unroll
            for (int mt = 0; mt < 2; ++mt)
                #pragma unroll
                for (int j = 0; j < 4; ++j) {
                    int pp = j >> 1, w = j & 1;
                    mma_bf16(c[mt][j], ah[mt], bh[pp][2 * w], bh[pp][2 * w + 1]);
                    mma_bf16(c[mt][j], ah[mt], bl[pp][2 * w], bl[pp][2 * w + 1]);
                    mma_bf16(c[mt][j], al[mt], bh[pp][2 * w], bh[pp][2 * w + 1]);
                }
        }

        int M = rend - (gbase + s * GE1);
        if (M > GE1) M = GE1;
        #pragma unroll
        for (int mt = 0; mt < 2; ++mt) {
            int rowA = 16 * mt + (lane >> 2);
            int myrow = evenp ? rowA : rowA + 8;
            bool ok = myrow < M;
            float* bp = g_x1acc + (size_t)sdst[grp][s & 1][ok ? myrow : 0] * HID;
            #pragma unroll
            for (int j = 0; j < 4; ++j) {
                float sx = evenp ? c[mt][j][2] : c[mt][j][0];
                float sy = evenp ? c[mt][j][3] : c[mt][j][1];
                float rx = __shfl_xor_sync(0xffffffffu, sx, 1);
                float ry = __shfl_xor_sync(0xffffffffu, sy, 1);
                if (ok) {
                    if (evenp)
                        red4(bp + nbase + 8 * j + 2 * t,
                             c[mt][j][0], c[mt][j][1], rx, ry);
                    else
                        red4(bp + nbase + 8 * j + 2 * (t - 1),
                             rx, ry, c[mt][j][2], c[mt][j][3]);
                }
            }
        }
    }
}

// ---------------- LN1 + ReLU -> bf16 hi/lo -----------------------------------
__global__ void k_ln1(const float* __restrict__ g, const float* __restrict__ bb, int N) {
    int w = (blockIdx.x * blockDim.x + threadIdx.x) >> 5;
    int lane = threadIdx.x & 31;
    if (w >= N) return;
    float4 v = ((const float4*)(g_x1acc + (size_t)w * HID))[lane];
    float s = v.x + v.y + v.z + v.w;
    #pragma unroll
    for (int o = 16; o; o >>= 1) s += __shfl_xor_sync(0xffffffffu, s, o);
    float mu = s * (1.f / HID);
    float dx = v.x - mu, dy = v.y - mu, dz = v.z - mu, dw = v.w - mu;
    float q = dx * dx + dy * dy + dz * dz + dw * dw;
    #pragma unroll
    for (int o = 16; o; o >>= 1) q += __shfl_xor_sync(0xffffffffu, q, o);
    float inv = rsqrtf(q * (1.f / HID) + 1e-5f);
    float4 gv = ((const float4*)g)[lane];
    float4 bv = ((const float4*)bb)[lane];
    float o0 = fmaxf(dx * inv * gv.x + bv.x, 0.f);
    float o1 = fmaxf(dy * inv * gv.y + bv.y, 0.f);
    float o2 = fmaxf(dz * inv * gv.z + bv.z, 0.f);
    float o3 = fmaxf(dw * inv * gv.w + bv.w, 0.f);
    __nv_bfloat16 h[4], l[4];
    split_bf16(o0, h[0], l[0]); split_bf16(o1, h[1], l[1]);
    split_bf16(o2, h[2], l[2]); split_bf16(o3, h[3], l[3]);
    ((uint2*)(g_x1h + (size_t)w * HID))[lane] = *(uint2*)h;
    ((uint2*)(g_x1l + (size_t)w * HID))[lane] = *(uint2*)l;
}

// ---------------- layer-2: 512 edges/block, 2 groups x 32-edge sub-tiles -----
#define PA2 136
#define PW2 72
#define GE2 32
#define SM2_WL   (128 * PW2)
#define SM2_A    (2 * 128 * PW2)
#define ABUF2    (2 * GE2 * PA2)
#define SMEM2_BYTES ((SM2_A + 4 * ABUF2) * 2)

__global__ void __launch_bounds__(256) k_gemm2() {
    extern __shared__ __nv_bfloat16 sm[];
    __nv_bfloat16* Wh = sm;
    __nv_bfloat16* Wl = sm + SM2_WL;
    __shared__ int sdst[2][2][GE2];

    int b = blockIdx.x;
    if (b >= g_tileoff[RNUM]) return;
    int tid = threadIdx.x;
    int r = 0;
    while (g_tileoff[r + 1] <= b) ++r;
    int base = g_off[r] + (b - g_tileoff[r]) * 512;
    int rend = g_off[r + 1];

    // stage W2[r] (commit bundled with first prefetch)
    {
        int row = tid >> 1, half = tid & 1;
        size_t src = ((size_t)r * HID + row) * DIN + half * 32;
        uint32_t dh = smem_u32(Wh + row * PW2 + half * 32);
        uint32_t dl = smem_u32(Wl + row * PW2 + half * 32);
        #pragma unroll
        for (int q = 0; q < 4; ++q) {
            cpasync16(dh + q * 16, g_w2h + src + q * 8);
            cpasync16(dl + q * 16, g_w2l + src + q * 8);
        }
    }

    int grp = tid >> 7, gtid = tid & 127;
    int gbase = base + grp * 256;
    int nsub = (rend - gbase + 31) >> 5;
    if (nsub > 8) nsub = 8;
    if (nsub < 0) nsub = 0;

    int e = gtid >> 2, p = gtid & 3;
    auto prefetch = [&](int ss, int bb) {
        int gi = gbase + ss * GE2 + e;
        int row = 0;
        bool v = gi < rend;
        if (v) row = g_esrc2[gi];
        if (p == 0) sdst[grp][bb][e] = v ? g_edst[gi] : 0;
        const __nv_bfloat16* sh = g_x1h + (size_t)row * HID + p * 32;
        const __nv_bfloat16* sl = g_x1l + (size_t)row * HID + p * 32;
        uint32_t dh = smem_u32(sm + SM2_A + (grp * 2 + bb) * ABUF2 + e * PA2 + p * 32);
        uint32_t dl = dh + (GE2 * PA2) * 2;
        #pragma unroll
        for (int q = 0; q < 4; ++q) {
            cpasync16(dh + q * 16, sh + q * 8);
            cpasync16(dl + q * 16, sl + q * 8);
        }
        cp_commit();
    };
    prefetch(0, 0);

    // block-wide barrier: W staged by all 256 threads, read by both groups
    cp_wait0();
    __syncthreads();

    int wid = gtid >> 5, lane = gtid & 31;     // wid 0..3 in group
    int nbase = 16 * wid;
    uint32_t aBase = smem_u32(sm + SM2_A + grp * 2 * ABUF2) +
        (((lane & 15) * PA2 + 8 * (lane >> 4)) << 1);
    uint32_t bOffH = smem_u32(Wh) +
        (((((lane & 7) + 8 * ((lane >> 3) & 1)) * PW2) + nbase + 8 * (lane >> 4)) << 1);
    uint32_t bOffL = bOffH + (SM2_WL << 1);

    int barid = grp + 1;

    // hoist this warp's 16-col W slice to registers
    uint32_t wbh[8][4], wbl[8][4];
    #pragma unroll
    for (int ks = 0; ks < 8; ++ks) {
        ldsm_x4t(wbh[ks], bOffH + ((ks * 16 * PW2) << 1));
        ldsm_x4t(wbl[ks], bOffL + ((ks * 16 * PW2) << 1));
    }

    int t = lane & 3;
    bool evenp = (t & 1) == 0;

    for (int s = 0; s < nsub; ++s) {
        if (s > 0) { cp_wait0(); bar_sync(barid, 128); }
        if (s + 1 < nsub) prefetch(s + 1, (s + 1) & 1);

        uint32_t aOffH = aBase + ((s & 1) * ABUF2 << 1);
        uint32_t aOffL = aOffH + ((GE2 * PA2) << 1);

        float c[2][2][4];
        #pragma unroll
        for (int mt = 0; mt < 2; ++mt)
            #pragma unroll
            for (int j = 0; j < 2; ++j)
                #pragma unroll
                for (int q = 0; q < 4; ++q) c[mt][j][q] = 0.f;

        #pragma unroll
        for (int ks = 0; ks < 8; ++ks) {
            int kk = ks * 16;
            uint32_t ah[2][4], al[2][4];
            #pragma unroll
            for (int mt = 0; mt < 2; ++mt) {
                ldsm_x4(ah[mt], aOffH + ((16 * mt * PA2 + kk) << 1));
                ldsm_x4(al[mt], aOffL + ((16 * mt * PA2 + kk) << 1));
            }
            #pragma unroll
            for (int mt = 0; mt < 2; ++mt)
                #pragma unroll
                for (int j = 0; j < 2; ++j) {
                    mma_bf16(c[mt][j], ah[mt], wbh[ks][2 * j], wbh[ks][2 * j + 1]);
                    mma_bf16(c[mt][j], ah[mt], wbl[ks][2 * j], wbl[ks][2 * j + 1]);
                    mma_bf16(c[mt][j], al[mt], wbh[ks][2 * j], wbh[ks][2 * j + 1]);
                }
        }

        int M = rend - (gbase + s * GE2);
        if (M > GE2) M = GE2;
        #pragma unroll
        for (int mt = 0; mt < 2; ++mt) {
            int rowA = 16 * mt + (lane >> 2);
            int myrow = evenp ? rowA : rowA + 8;
            bool ok = myrow < M;
            float* bp = g_x2acc + (size_t)sdst[grp][s & 1][ok ? myrow : 0] * DIN;
            #pragma unroll
            for (int j = 0; j < 2; ++j) {
                float sx = evenp ? c[mt][j][2] : c[mt][j][0];
                float sy = evenp ? c[mt][j][3] : c[mt][j][1];
                float rx = __shfl_xor_sync(0xffffffffu, sx, 1);
                float ry = __shfl_xor_sync(0xffffffffu, sy, 1);
                if (ok) {
                    if (evenp)
                        red4(bp + nbase + 8 * j + 2 * t,
                             c[mt][j][0], c[mt][j][1], rx, ry);
                    else
                        red4(bp + nbase + 8 * j + 2 * (t - 1),
                             rx, ry, c[mt][j][2], c[mt][j][3]);
                }
            }
        }
    }
}

// ---------------- LN2 + residual ---------------------------------------------
__global__ void k_ln2res(const int* __restrict__ nid, const float* __restrict__ emb,
                         const float* __restrict__ g, const float* __restrict__ bb,
                         float* __restrict__ out, int N) {
    int w = (blockIdx.x * blockDim.x + threadIdx.x) >> 5;
    int lane = threadIdx.x & 31;
    if (w >= N) return;
    float2 v = ((const float2*)(g_x2acc + (size_t)w * DIN))[lane];
    float s = v.x + v.y;
    #pragma unroll
    for (int o = 16; o; o >>= 1) s += __shfl_xor_sync(0xffffffffu, s, o);
    float mu = s * (1.f / DIN);
    float dx = v.x - mu, dy = v.y - mu;
    float q = dx * dx + dy * dy;
    #pragma unroll
    for (int o = 16; o; o >>= 1) q += __shfl_xor_sync(0xffffffffu, q, o);
    float inv = rsqrtf(q * (1.f / DIN) + 1e-5f);
    float2 gv = ((const float2*)g)[lane];
    float2 bv = ((const float2*)bb)[lane];
    float2 xr = ((const float2*)(emb + (size_t)nid[w] * DIN))[lane];
    float2 o2;
    o2.x = dx * inv * gv.x + bv.x + xr.x;
    o2.y = dy * inv * gv.y + bv.y + xr.y;
    ((float2*)(out + (size_t)w * DIN))[lane] = o2;
}

// ---------------- launch -----------------------------------------------------
extern "C" void kernel_launch(void* const* d_in, const int* in_sizes, int n_in,
                              void* d_out, int out_size) {
    const int*   nid   = (const int*)d_in[0];
    const int*   eidx  = (const int*)d_in[1];
    const int*   etype = (const int*)d_in[2];
    const float* emb   = (const float*)d_in[3];
    const float* W1    = (const float*)d_in[4];
    const float* W2    = (const float*)d_in[5];
    const float* ln1g  = (const float*)d_in[6];
    const float* ln1b  = (const float*)d_in[7];
    const float* ln2g  = (const float*)d_in[8];
    const float* ln2b  = (const float*)d_in[9];
    float* out = (float*)d_out;

    int N = in_sizes[0];
    int E = in_sizes[2];

    cudaFuncSetAttribute(k_gemm1, cudaFuncAttributeMaxDynamicSharedMemorySize, SMEM1_BYTES);
    cudaFuncSetAttribute(k_gemm2, cudaFuncAttributeMaxDynamicSharedMemorySize, SMEM2_BYTES);

    int blocks = (E + 511) / 512 + RNUM;

    k_prep<<<1024, 256>>>(emb, W1, W2, etype, N, E);
    k_scan<<<1, 32>>>();
    k_bucket<<<(E + 255) / 256, 256>>>(etype, eidx, nid, E);
    k_gemm1<<<blocks, 256, SMEM1_BYTES>>>();
    k_ln1<<<(N * 32 + 255) / 256, 256>>>(ln1g, ln1b, N);
    k_gemm2<<<blocks, 256, SMEM2_BYTES>>>();
    k_ln2res<<<(N * 32 + 255) / 256, 256>>>(nid, emb, ln2g, ln2b, out, N);
}

// round 13
// speedup vs baseline: 1.4530x; 1.0332x over previous
#include <cuda_runtime.h>
#include <cuda_fp16.h>
#include <cstdint>

#define MAXN 50000
#define MAXE 600000
#define RNUM 16
#define DIN  64
#define HID  128

// ---------------- scratch ----------------------------------------------------
__device__ float g_x1acc[(size_t)MAXN * HID];
__device__ float g_x2acc[(size_t)MAXN * DIN];
__device__ __half g_embh[(size_t)MAXN * DIN];
__device__ __half g_embl[(size_t)MAXN * DIN];
__device__ __half g_x1h[(size_t)MAXN * HID];
__device__ __half g_x1l[(size_t)MAXN * HID];
__device__ __half g_w1h[RNUM * DIN * HID];     // single fp16 (no lo)
__device__ __half g_w2h[RNUM * HID * DIN];
__device__ int g_esrc1[MAXE];
__device__ int g_esrc2[MAXE];
__device__ int g_edst[MAXE];
__device__ int g_cnt[RNUM];          // zero at load; k_scan consumes AND resets
__device__ int g_off[RNUM + 1];
__device__ int g_cursor[RNUM];
__device__ int g_tileoff[RNUM + 1];

// ---------------- PTX helpers ------------------------------------------------
__device__ __forceinline__ uint32_t smem_u32(const void* p) {
    return (uint32_t)__cvta_generic_to_shared(p);
}
__device__ __forceinline__ void ldsm_x4(uint32_t* r, uint32_t a) {
    asm volatile("ldmatrix.sync.aligned.m8n8.x4.shared.b16 {%0,%1,%2,%3}, [%4];\n"
                 : "=r"(r[0]), "=r"(r[1]), "=r"(r[2]), "=r"(r[3]) : "r"(a));
}
__device__ __forceinline__ void ldsm_x4t(uint32_t* r, uint32_t a) {
    asm volatile("ldmatrix.sync.aligned.m8n8.x4.trans.shared.b16 {%0,%1,%2,%3}, [%4];\n"
                 : "=r"(r[0]), "=r"(r[1]), "=r"(r[2]), "=r"(r[3]) : "r"(a));
}
__device__ __forceinline__ void mma_f16(float* c, const uint32_t* a, uint32_t b0, uint32_t b1) {
    asm volatile("mma.sync.aligned.m16n8k16.row.col.f32.f16.f16.f32 "
                 "{%0,%1,%2,%3},{%4,%5,%6,%7},{%8,%9},{%0,%1,%2,%3};\n"
                 : "+f"(c[0]), "+f"(c[1]), "+f"(c[2]), "+f"(c[3])
                 : "r"(a[0]), "r"(a[1]), "r"(a[2]), "r"(a[3]), "r"(b0), "r"(b1));
}
__device__ __forceinline__ void cpasync16(uint32_t saddr, const void* g) {
    asm volatile("cp.async.cg.shared.global [%0], [%1], 16;\n" :: "r"(saddr), "l"(g));
}
__device__ __forceinline__ void cp_commit() {
    asm volatile("cp.async.commit_group;\n");
}
__device__ __forceinline__ void cp_wait0() {
    asm volatile("cp.async.wait_group 0;\n");
}
__device__ __forceinline__ void bar_sync(int id, int n) {
    asm volatile("bar.sync %0, %1;\n" :: "r"(id), "r"(n) : "memory");
}
__device__ __forceinline__ void red4(float* p, float x, float y, float z, float w) {
    asm volatile("red.global.add.v4.f32 [%0], {%1,%2,%3,%4};\n"
                 :: "l"(p), "f"(x), "f"(y), "f"(z), "f"(w) : "memory");
}
__device__ __forceinline__ void split_fp16(float v, __half& h, __half& l) {
    h = __float2half(v);
    l = __float2half(v - __half2float(h));
}

// ---------------- prep: zero + convert + relation hist (fused) ---------------
__global__ void k_prep(const float* __restrict__ emb, const float* __restrict__ W1,
                       const float* __restrict__ W2, const int* __restrict__ et,
                       int N, int E) {
    __shared__ int s[RNUM];
    if (threadIdx.x < RNUM) s[threadIdx.x] = 0;
    __syncthreads();
    int stride = gridDim.x * blockDim.x;
    int i = blockIdx.x * blockDim.x + threadIdx.x;
    float4 z = make_float4(0.f, 0.f, 0.f, 0.f);
    int n1 = N * (HID / 4);
    for (int k = i; k < n1; k += stride) ((float4*)g_x1acc)[k] = z;
    int n2 = N * (DIN / 4);
    for (int k = i; k < n2; k += stride) ((float4*)g_x2acc)[k] = z;
    int ne = N * DIN;
    for (int k = i; k < ne; k += stride) split_fp16(emb[k], g_embh[k], g_embl[k]);
    for (int k = i; k < RNUM * DIN * HID; k += stride) g_w1h[k] = __float2half(W1[k]);
    for (int k = i; k < RNUM * HID * DIN; k += stride) g_w2h[k] = __float2half(W2[k]);
    for (int k = i; k < E; k += stride) atomicAdd(&s[et[k]], 1);
    __syncthreads();
    if (threadIdx.x < RNUM && s[threadIdx.x]) atomicAdd(&g_cnt[threadIdx.x], s[threadIdx.x]);
}

// ---------------- scan (consume + reset g_cnt) --------------------------------
__global__ void k_scan() {
    if (threadIdx.x == 0 && blockIdx.x == 0) {
        int o = 0, t = 0;
        for (int r = 0; r < RNUM; ++r) {
            g_off[r] = o; g_cursor[r] = o; g_tileoff[r] = t;
            o += g_cnt[r];
            t += (g_cnt[r] + 511) >> 9;        // 512-edge blocks
            g_cnt[r] = 0;
        }
        g_off[RNUM] = o; g_tileoff[RNUM] = t;
    }
}
__global__ void k_bucket(const int* __restrict__ et, const int* __restrict__ eidx,
                         const int* __restrict__ nid, int E) {
    __shared__ int lcnt[RNUM], lbase[RNUM];
    int e = blockIdx.x * 256 + threadIdx.x;
    if (threadIdx.x < RNUM) lcnt[threadIdx.x] = 0;
    __syncthreads();
    int r = 0, rank = 0, s = 0, d = 0;
    if (e < E) {
        r = et[e]; s = eidx[e]; d = eidx[E + e];
        rank = atomicAdd(&lcnt[r], 1);
    }
    __syncthreads();
    if (threadIdx.x < RNUM && lcnt[threadIdx.x])
        lbase[threadIdx.x] = atomicAdd(&g_cursor[threadIdx.x], lcnt[threadIdx.x]);
    __syncthreads();
    if (e < E) {
        int pos = lbase[r] + rank;
        g_esrc1[pos] = nid[s];
        g_esrc2[pos] = s;
        g_edst[pos]  = d;
    }
}

// ---------------- layer-1: 512 edges/block, 2 groups x 32-edge sub-tiles -----
#define PA1 72
#define PW1 136
#define GE1 32
#define SM1_A    (64 * PW1)                  // W hi only
#define ABUF1    (2 * GE1 * PA1)             // hi+lo per 32-edge buffer
#define SMEM1_BYTES ((SM1_A + 4 * ABUF1) * 2)

__global__ void __launch_bounds__(256) k_gemm1() {
    extern __shared__ __half sm[];
    __half* Wh = sm;
    __shared__ int sdst[2][2][GE1];

    int b = blockIdx.x;
    if (b >= g_tileoff[RNUM]) return;
    int tid = threadIdx.x;
    int r = 0;
    while (g_tileoff[r + 1] <= b) ++r;
    int base = g_off[r] + (b - g_tileoff[r]) * 512;
    int rend = g_off[r + 1];

    // stage W1[r] hi (commit bundled with first prefetch)
    {
        int row = tid >> 2, seg = tid & 3;
        size_t src = ((size_t)r * DIN + row) * HID + seg * 32;
        uint32_t dh = smem_u32(Wh + row * PW1 + seg * 32);
        #pragma unroll
        for (int q = 0; q < 4; ++q)
            cpasync16(dh + q * 16, g_w1h + src + q * 8);
    }

    int grp = tid >> 7, gtid = tid & 127;
    int gbase = base + grp * 256;
    int nsub = (rend - gbase + 31) >> 5;
    if (nsub > 8) nsub = 8;
    if (nsub < 0) nsub = 0;

    int e = gtid >> 2, p = gtid & 3;
    auto prefetch = [&](int ss, int bb) {
        int gi = gbase + ss * GE1 + e;
        int row = 0;
        bool v = gi < rend;
        if (v) row = g_esrc1[gi];
        if (p == 0) sdst[grp][bb][e] = v ? g_edst[gi] : 0;
        const __half* sh = g_embh + (size_t)row * DIN + p * 16;
        const __half* sl = g_embl + (size_t)row * DIN + p * 16;
        uint32_t dh = smem_u32(sm + SM1_A + (grp * 2 + bb) * ABUF1 + e * PA1 + p * 16);
        uint32_t dl = dh + (GE1 * PA1) * 2;
        cpasync16(dh, sh); cpasync16(dh + 16, sh + 8);
        cpasync16(dl, sl); cpasync16(dl + 16, sl + 8);
        cp_commit();
    };
    prefetch(0, 0);      // commits W + first A tile

    // W staged by all 256 threads, read by both groups: block-wide barrier once
    cp_wait0();
    __syncthreads();

    int wid = gtid >> 5, lane = gtid & 31;
    int nbase = 32 * wid;
    uint32_t aBase = smem_u32(sm + SM1_A + grp * 2 * ABUF1) +
        (((lane & 15) * PA1 + 8 * (lane >> 4)) << 1);
    uint32_t bOffH = smem_u32(Wh) +
        (((((lane & 7) + 8 * ((lane >> 3) & 1)) * PW1) + nbase + 8 * (lane >> 4)) << 1);

    int t = lane & 3;
    bool evenp = (t & 1) == 0;
    int barid = grp + 1;

    for (int s = 0; s < nsub; ++s) {
        if (s > 0) { cp_wait0(); bar_sync(barid, 128); }
        if (s + 1 < nsub) prefetch(s + 1, (s + 1) & 1);

        uint32_t aOffH = aBase + ((s & 1) * ABUF1 << 1);
        uint32_t aOffL = aOffH + ((GE1 * PA1) << 1);

        float c[2][4][4];
        #pragma unroll
        for (int mt = 0; mt < 2; ++mt)
            #pragma unroll
            for (int j = 0; j < 4; ++j)
                #pragma unroll
                for (int q = 0; q < 4; ++q) c[mt][j][q] = 0.f;

        #pragma unroll
        for (int ks = 0; ks < 4; ++ks) {
            int kk = ks * 16;
            uint32_t ah[2][4], al[2][4], bh[2][4];
            #pragma unroll
            for (int mt = 0; mt < 2; ++mt) {
                ldsm_x4(ah[mt], aOffH + ((16 * mt * PA1 + kk) << 1));
                ldsm_x4(al[mt], aOffL + ((16 * mt * PA1 + kk) << 1));
            }
            #pragma unroll
            for (int pp = 0; pp < 2; ++pp)
                ldsm_x4t(bh[pp], bOffH + ((kk * PW1) << 1) + pp * 32);
            #pragma unroll
            for (int mt = 0; mt < 2; ++mt)
                #pragma unroll
                for (int j = 0; j < 4; ++j) {
                    int pp = j >> 1, w = j & 1;
                    mma_f16(c[mt][j], ah[mt], bh[pp][2 * w], bh[pp][2 * w + 1]);
                    mma_f16(c[mt][j], al[mt], bh[pp][2 * w], bh[pp][2 * w + 1]);
                }
        }

        int M = rend - (gbase + s * GE1);
        if (M > GE1) M = GE1;
        #pragma unroll
        for (int mt = 0; mt < 2; ++mt) {
            int rowA = 16 * mt + (lane >> 2);
            int myrow = evenp ? rowA : rowA + 8;
            bool ok = myrow < M;
            float* bp = g_x1acc + (size_t)sdst[grp][s & 1][ok ? myrow : 0] * HID;
            #pragma unroll
            for (int j = 0; j < 4; ++j) {
                float sx = evenp ? c[mt][j][2] : c[mt][j][0];
                float sy = evenp ? c[mt][j][3] : c[mt][j][1];
                float rx = __shfl_xor_sync(0xffffffffu, sx, 1);
                float ry = __shfl_xor_sync(0xffffffffu, sy, 1);
                if (ok) {
                    if (evenp)
                        red4(bp + nbase + 8 * j + 2 * t,
                             c[mt][j][0], c[mt][j][1], rx, ry);
                    else
                        red4(bp + nbase + 8 * j + 2 * (t - 1),
                             rx, ry, c[mt][j][2], c[mt][j][3]);
                }
            }
        }
    }
}

// ---------------- LN1 + ReLU -> fp16 hi/lo -----------------------------------
__global__ void k_ln1(const float* __restrict__ g, const float* __restrict__ bb, int N) {
    int w = (blockIdx.x * blockDim.x + threadIdx.x) >> 5;
    int lane = threadIdx.x & 31;
    if (w >= N) return;
    float4 v = ((const float4*)(g_x1acc + (size_t)w * HID))[lane];
    float s = v.x + v.y + v.z + v.w;
    #pragma unroll
    for (int o = 16; o; o >>= 1) s += __shfl_xor_sync(0xffffffffu, s, o);
    float mu = s * (1.f / HID);
    float dx = v.x - mu, dy = v.y - mu, dz = v.z - mu, dw = v.w - mu;
    float q = dx * dx + dy * dy + dz * dz + dw * dw;
    #pragma unroll
    for (int o = 16; o; o >>= 1) q += __shfl_xor_sync(0xffffffffu, q, o);
    float inv = rsqrtf(q * (1.f / HID) + 1e-5f);
    float4 gv = ((const float4*)g)[lane];
    float4 bv = ((const float4*)bb)[lane];
    float o0 = fmaxf(dx * inv * gv.x + bv.x, 0.f);
    float o1 = fmaxf(dy * inv * gv.y + bv.y, 0.f);
    float o2 = fmaxf(dz * inv * gv.z + bv.z, 0.f);
    float o3 = fmaxf(dw * inv * gv.w + bv.w, 0.f);
    __half h[4], l[4];
    split_fp16(o0, h[0], l[0]); split_fp16(o1, h[1], l[1]);
    split_fp16(o2, h[2], l[2]); split_fp16(o3, h[3], l[3]);
    ((uint2*)(g_x1h + (size_t)w * HID))[lane] = *(uint2*)h;
    ((uint2*)(g_x1l + (size_t)w * HID))[lane] = *(uint2*)l;
}

// ---------------- layer-2: 512 edges/block, 2 groups x 32-edge sub-tiles -----
#define PA2 136
#define PW2 72
#define GE2 32
#define SM2_A    (128 * PW2)                 // W hi only
#define ABUF2    (2 * GE2 * PA2)
#define SMEM2_BYTES ((SM2_A + 4 * ABUF2) * 2)

__global__ void __launch_bounds__(256) k_gemm2() {
    extern __shared__ __half sm[];
    __half* Wh = sm;
    __shared__ int sdst[2][2][GE2];

    int b = blockIdx.x;
    if (b >= g_tileoff[RNUM]) return;
    int tid = threadIdx.x;
    int r = 0;
    while (g_tileoff[r + 1] <= b) ++r;
    int base = g_off[r] + (b - g_tileoff[r]) * 512;
    int rend = g_off[r + 1];

    // stage W2[r] hi (commit bundled with first prefetch)
    {
        int row = tid >> 1, half = tid & 1;
        size_t src = ((size_t)r * HID + row) * DIN + half * 32;
        uint32_t dh = smem_u32(Wh + row * PW2 + half * 32);
        #pragma unroll
        for (int q = 0; q < 4; ++q)
            cpasync16(dh + q * 16, g_w2h + src + q * 8);
    }

    int grp = tid >> 7, gtid = tid & 127;
    int gbase = base + grp * 256;
    int nsub = (rend - gbase + 31) >> 5;
    if (nsub > 8) nsub = 8;
    if (nsub < 0) nsub = 0;

    int e = gtid >> 2, p = gtid & 3;
    auto prefetch = [&](int ss, int bb) {
        int gi = gbase + ss * GE2 + e;
        int row = 0;
        bool v = gi < rend;
        if (v) row = g_esrc2[gi];
        if (p == 0) sdst[grp][bb][e] = v ? g_edst[gi] : 0;
        const __half* sh = g_x1h + (size_t)row * HID + p * 32;
        const __half* sl = g_x1l + (size_t)row * HID + p * 32;
        uint32_t dh = smem_u32(sm + SM2_A + (grp * 2 + bb) * ABUF2 + e * PA2 + p * 32);
        uint32_t dl = dh + (GE2 * PA2) * 2;
        #pragma unroll
        for (int q = 0; q < 4; ++q) {
            cpasync16(dh + q * 16, sh + q * 8);
            cpasync16(dl + q * 16, sl + q * 8);
        }
        cp_commit();
    };
    prefetch(0, 0);

    // block-wide barrier: W staged by all 256 threads, read by both groups
    cp_wait0();
    __syncthreads();

    int wid = gtid >> 5, lane = gtid & 31;
    int nbase = 16 * wid;
    uint32_t aBase = smem_u32(sm + SM2_A + grp * 2 * ABUF2) +
        (((lane & 15) * PA2 + 8 * (lane >> 4)) << 1);
    uint32_t bOffH = smem_u32(Wh) +
        (((((lane & 7) + 8 * ((lane >> 3) & 1)) * PW2) + nbase + 8 * (lane >> 4)) << 1);

    int barid = grp + 1;

    // hoist this warp's 16-col W slice (hi only) to registers
    uint32_t wbh[8][4];
    #pragma unroll
    for (int ks = 0; ks < 8; ++ks)
        ldsm_x4t(wbh[ks], bOffH + ((ks * 16 * PW2) << 1));

    int t = lane & 3;
    bool evenp = (t & 1) == 0;

    for (int s = 0; s < nsub; ++s) {
        if (s > 0) { cp_wait0(); bar_sync(barid, 128); }
        if (s + 1 < nsub) prefetch(s + 1, (s + 1) & 1);

        uint32_t aOffH = aBase + ((s & 1) * ABUF2 << 1);
        uint32_t aOffL = aOffH + ((GE2 * PA2) << 1);

        float c[2][2][4];
        #pragma unroll
        for (int mt = 0; mt < 2; ++mt)
            #pragma unroll
            for (int j = 0; j < 2; ++j)
                #pragma unroll
                for (int q = 0; q < 4; ++q) c[mt][j][q] = 0.f;

        #pragma unroll
        for (int ks = 0; ks < 8; ++ks) {
            int kk = ks * 16;
            uint32_t ah[2][4], al[2][4];
            #pragma unroll
            for (int mt = 0; mt < 2; ++mt) {
                ldsm_x4(ah[mt], aOffH + ((16 * mt * PA2 + kk) << 1));
                ldsm_x4(al[mt], aOffL + ((16 * mt * PA2 + kk) << 1));
            }
            #pragma unroll
            for (int mt = 0; mt < 2; ++mt)
                #pragma unroll
                for (int j = 0; j < 2; ++j) {
                    mma_f16(c[mt][j], ah[mt], wbh[ks][2 * j], wbh[ks][2 * j + 1]);
                    mma_f16(c[mt][j], al[mt], wbh[ks][2 * j], wbh[ks][2 * j + 1]);
                }
        }

        int M = rend - (gbase + s * GE2);
        if (M > GE2) M = GE2;
        #pragma unroll
        for (int mt = 0; mt < 2; ++mt) {
            int rowA = 16 * mt + (lane >> 2);
            int myrow = evenp ? rowA : rowA + 8;
            bool ok = myrow < M;
            float* bp = g_x2acc + (size_t)sdst[grp][s & 1][ok ? myrow : 0] * DIN;
            #pragma unroll
            for (int j = 0; j < 2; ++j) {
                float sx = evenp ? c[mt][j][2] : c[mt][j][0];
                float sy = evenp ? c[mt][j][3] : c[mt][j][1];
                float rx = __shfl_xor_sync(0xffffffffu, sx, 1);
                float ry = __shfl_xor_sync(0xffffffffu, sy, 1);
                if (ok) {
                    if (evenp)
                        red4(bp + nbase + 8 * j + 2 * t,
                             c[mt][j][0], c[mt][j][1], rx, ry);
                    else
                        red4(bp + nbase + 8 * j + 2 * (t - 1),
                             rx, ry, c[mt][j][2], c[mt][j][3]);
                }
            }
        }
    }
}

// ---------------- LN2 + residual ---------------------------------------------
__global__ void k_ln2res(const int* __restrict__ nid, const float* __restrict__ emb,
                         const float* __restrict__ g, const float* __restrict__ bb,
                         float* __restrict__ out, int N) {
    int w = (blockIdx.x * blockDim.x + threadIdx.x) >> 5;
    int lane = threadIdx.x & 31;
    if (w >= N) return;
    float2 v = ((const float2*)(g_x2acc + (size_t)w * DIN))[lane];
    float s = v.x + v.y;
    #pragma unroll
    for (int o = 16; o; o >>= 1) s += __shfl_xor_sync(0xffffffffu, s, o);
    float mu = s * (1.f / DIN);
    float dx = v.x - mu, dy = v.y - mu;
    float q = dx * dx + dy * dy;
    #pragma unroll
    for (int o = 16; o; o >>= 1) q += __shfl_xor_sync(0xffffffffu, q, o);
    float inv = rsqrtf(q * (1.f / DIN) + 1e-5f);
    float2 gv = ((const float2*)g)[lane];
    float2 bv = ((const float2*)bb)[lane];
    float2 xr = ((const float2*)(emb + (size_t)nid[w] * DIN))[lane];
    float2 o2;
    o2.x = dx * inv * gv.x + bv.x + xr.x;
    o2.y = dy * inv * gv.y + bv.y + xr.y;
    ((float2*)(out + (size_t)w * DIN))[lane] = o2;
}

// ---------------- launch -----------------------------------------------------
extern "C" void kernel_launch(void* const* d_in, const int* in_sizes, int n_in,
                              void* d_out, int out_size) {
    const int*   nid   = (const int*)d_in[0];
    const int*   eidx  = (const int*)d_in[1];
    const int*   etype = (const int*)d_in[2];
    const float* emb   = (const float*)d_in[3];
    const float* W1    = (const float*)d_in[4];
    const float* W2    = (const float*)d_in[5];
    const float* ln1g  = (const float*)d_in[6];
    const float* ln1b  = (const float*)d_in[7];
    const float* ln2g  = (const float*)d_in[8];
    const float* ln2b  = (const float*)d_in[9];
    float* out = (float*)d_out;

    int N = in_sizes[0];
    int E = in_sizes[2];

    cudaFuncSetAttribute(k_gemm1, cudaFuncAttributeMaxDynamicSharedMemorySize, SMEM1_BYTES);
    cudaFuncSetAttribute(k_gemm2, cudaFuncAttributeMaxDynamicSharedMemorySize, SMEM2_BYTES);

    int blocks = (E + 511) / 512 + RNUM;

    k_prep<<<1024, 256>>>(emb, W1, W2, etype, N, E);
    k_scan<<<1, 32>>>();
    k_bucket<<<(E + 255) / 256, 256>>>(etype, eidx, nid, E);
    k_gemm1<<<blocks, 256, SMEM1_BYTES>>>();
    k_ln1<<<(N * 32 + 255) / 256, 256>>>(ln1g, ln1b, N);
    k_gemm2<<<blocks, 256, SMEM2_BYTES>>>();
    k_ln2res<<<(N * 32 + 255) / 256, 256>>>(nid, emb, ln2g, ln2b, out, N);
}

// round 14
// speedup vs baseline: 1.8445x; 1.2695x over previous
#include <cuda_runtime.h>
#include <cuda_fp16.h>
#include <cstdint>

#define MAXN 50000
#define MAXE 600000
#define RNUM 16
#define DIN  64
#define HID  128

// ---------------- scratch ----------------------------------------------------
__device__ float g_x1acc[(size_t)MAXN * HID];
__device__ float g_x2acc[(size_t)MAXN * DIN];
__device__ __half g_embh[(size_t)MAXN * DIN];
__device__ __half g_x1h[(size_t)MAXN * HID];
__device__ __half g_w1h[RNUM * DIN * HID];
__device__ __half g_w2h[RNUM * HID * DIN];
__device__ int g_esrc1[MAXE];
__device__ int g_esrc2[MAXE];
__device__ int g_edst[MAXE];
__device__ int g_cnt[RNUM];          // zero at load; k_scan consumes AND resets
__device__ int g_off[RNUM + 1];
__device__ int g_cursor[RNUM];
__device__ int g_tileoff[RNUM + 1];

// ---------------- PTX helpers ------------------------------------------------
__device__ __forceinline__ uint32_t smem_u32(const void* p) {
    return (uint32_t)__cvta_generic_to_shared(p);
}
__device__ __forceinline__ void ldsm_x4(uint32_t* r, uint32_t a) {
    asm volatile("ldmatrix.sync.aligned.m8n8.x4.shared.b16 {%0,%1,%2,%3}, [%4];\n"
                 : "=r"(r[0]), "=r"(r[1]), "=r"(r[2]), "=r"(r[3]) : "r"(a));
}
__device__ __forceinline__ void ldsm_x4t(uint32_t* r, uint32_t a) {
    asm volatile("ldmatrix.sync.aligned.m8n8.x4.trans.shared.b16 {%0,%1,%2,%3}, [%4];\n"
                 : "=r"(r[0]), "=r"(r[1]), "=r"(r[2]), "=r"(r[3]) : "r"(a));
}
__device__ __forceinline__ void mma_f16(float* c, const uint32_t* a, uint32_t b0, uint32_t b1) {
    asm volatile("mma.sync.aligned.m16n8k16.row.col.f32.f16.f16.f32 "
                 "{%0,%1,%2,%3},{%4,%5,%6,%7},{%8,%9},{%0,%1,%2,%3};\n"
                 : "+f"(c[0]), "+f"(c[1]), "+f"(c[2]), "+f"(c[3])
                 : "r"(a[0]), "r"(a[1]), "r"(a[2]), "r"(a[3]), "r"(b0), "r"(b1));
}
__device__ __forceinline__ void cpasync16(uint32_t saddr, const void* g) {
    asm volatile("cp.async.cg.shared.global [%0], [%1], 16;\n" :: "r"(saddr), "l"(g));
}
__device__ __forceinline__ void cp_commit() {
    asm volatile("cp.async.commit_group;\n");
}
__device__ __forceinline__ void cp_wait0() {
    asm volatile("cp.async.wait_group 0;\n");
}
__device__ __forceinline__ void bar_sync(int id, int n) {
    asm volatile("bar.sync %0, %1;\n" :: "r"(id), "r"(n) : "memory");
}
__device__ __forceinline__ void red4(float* p, float x, float y, float z, float w) {
    asm volatile("red.global.add.v4.f32 [%0], {%1,%2,%3,%4};\n"
                 :: "l"(p), "f"(x), "f"(y), "f"(z), "f"(w) : "memory");
}

// ---------------- prep: zero + convert + relation hist (fused) ---------------
__global__ void k_prep(const float* __restrict__ emb, const float* __restrict__ W1,
                       const float* __restrict__ W2, const int* __restrict__ et,
                       int N, int E) {
    __shared__ int s[RNUM];
    if (threadIdx.x < RNUM) s[threadIdx.x] = 0;
    __syncthreads();
    int stride = gridDim.x * blockDim.x;
    int i = blockIdx.x * blockDim.x + threadIdx.x;
    float4 z = make_float4(0.f, 0.f, 0.f, 0.f);
    int n1 = N * (HID / 4);
    for (int k = i; k < n1; k += stride) ((float4*)g_x1acc)[k] = z;
    int n2 = N * (DIN / 4);
    for (int k = i; k < n2; k += stride) ((float4*)g_x2acc)[k] = z;
    int ne = N * DIN;
    for (int k = i; k < ne; k += stride) g_embh[k] = __float2half(emb[k]);
    for (int k = i; k < RNUM * DIN * HID; k += stride) g_w1h[k] = __float2half(W1[k]);
    for (int k = i; k < RNUM * HID * DIN; k += stride) g_w2h[k] = __float2half(W2[k]);
    for (int k = i; k < E; k += stride) atomicAdd(&s[et[k]], 1);
    __syncthreads();
    if (threadIdx.x < RNUM && s[threadIdx.x]) atomicAdd(&g_cnt[threadIdx.x], s[threadIdx.x]);
}

// ---------------- scan (consume + reset g_cnt) --------------------------------
__global__ void k_scan() {
    if (threadIdx.x == 0 && blockIdx.x == 0) {
        int o = 0, t = 0;
        for (int r = 0; r < RNUM; ++r) {
            g_off[r] = o; g_cursor[r] = o; g_tileoff[r] = t;
            o += g_cnt[r];
            t += (g_cnt[r] + 511) >> 9;        // 512-edge blocks
            g_cnt[r] = 0;
        }
        g_off[RNUM] = o; g_tileoff[RNUM] = t;
    }
}
__global__ void k_bucket(const int* __restrict__ et, const int* __restrict__ eidx,
                         const int* __restrict__ nid, int E) {
    __shared__ int lcnt[RNUM], lbase[RNUM];
    int e = blockIdx.x * 256 + threadIdx.x;
    if (threadIdx.x < RNUM) lcnt[threadIdx.x] = 0;
    __syncthreads();
    int r = 0, rank = 0, s = 0, d = 0;
    if (e < E) {
        r = et[e]; s = eidx[e]; d = eidx[E + e];
        rank = atomicAdd(&lcnt[r], 1);
    }
    __syncthreads();
    if (threadIdx.x < RNUM && lcnt[threadIdx.x])
        lbase[threadIdx.x] = atomicAdd(&g_cursor[threadIdx.x], lcnt[threadIdx.x]);
    __syncthreads();
    if (e < E) {
        int pos = lbase[r] + rank;
        g_esrc1[pos] = nid[s];
        g_esrc2[pos] = s;
        g_edst[pos]  = d;
    }
}

// ---------------- layer-1: 512 edges/block, 2 groups x 32-edge sub-tiles -----
#define PA1 72
#define PW1 136
#define GE1 32
#define SM1_A    (64 * PW1)                  // W hi only
#define ABUF1    (GE1 * PA1)                 // single plane per 32-edge buffer
#define SMEM1_BYTES ((SM1_A + 4 * ABUF1) * 2)

__global__ void __launch_bounds__(256) k_gemm1() {
    extern __shared__ __half sm[];
    __half* Wh = sm;
    __shared__ int sdst[2][2][GE1];

    int b = blockIdx.x;
    if (b >= g_tileoff[RNUM]) return;
    int tid = threadIdx.x;
    int r = 0;
    while (g_tileoff[r + 1] <= b) ++r;
    int base = g_off[r] + (b - g_tileoff[r]) * 512;
    int rend = g_off[r + 1];

    // stage W1[r] (commit bundled with first prefetch)
    {
        int row = tid >> 2, seg = tid & 3;
        size_t src = ((size_t)r * DIN + row) * HID + seg * 32;
        uint32_t dh = smem_u32(Wh + row * PW1 + seg * 32);
        #pragma unroll
        for (int q = 0; q < 4; ++q)
            cpasync16(dh + q * 16, g_w1h + src + q * 8);
    }

    int grp = tid >> 7, gtid = tid & 127;
    int gbase = base + grp * 256;
    int nsub = (rend - gbase + 31) >> 5;
    if (nsub > 8) nsub = 8;
    if (nsub < 0) nsub = 0;

    int e = gtid >> 2, p = gtid & 3;
    auto prefetch = [&](int ss, int bb) {
        int gi = gbase + ss * GE1 + e;
        int row = 0;
        bool v = gi < rend;
        if (v) row = g_esrc1[gi];
        if (p == 0) sdst[grp][bb][e] = v ? g_edst[gi] : 0;
        const __half* sh = g_embh + (size_t)row * DIN + p * 16;
        uint32_t dh = smem_u32(sm + SM1_A + (grp * 2 + bb) * ABUF1 + e * PA1 + p * 16);
        cpasync16(dh, sh); cpasync16(dh + 16, sh + 8);
        cp_commit();
    };
    prefetch(0, 0);      // commits W + first A tile

    // W staged by all 256 threads, read by both groups: block-wide barrier once
    cp_wait0();
    __syncthreads();

    int wid = gtid >> 5, lane = gtid & 31;
    int nbase = 32 * wid;
    uint32_t aBase = smem_u32(sm + SM1_A + grp * 2 * ABUF1) +
        (((lane & 15) * PA1 + 8 * (lane >> 4)) << 1);
    uint32_t bOffH = smem_u32(Wh) +
        (((((lane & 7) + 8 * ((lane >> 3) & 1)) * PW1) + nbase + 8 * (lane >> 4)) << 1);

    int t = lane & 3;
    bool evenp = (t & 1) == 0;
    int barid = grp + 1;

    for (int s = 0; s < nsub; ++s) {
        if (s > 0) { cp_wait0(); bar_sync(barid, 128); }
        if (s + 1 < nsub) prefetch(s + 1, (s + 1) & 1);

        uint32_t aOffH = aBase + ((s & 1) * ABUF1 << 1);

        float c[2][4][4];
        #pragma unroll
        for (int mt = 0; mt < 2; ++mt)
            #pragma unroll
            for (int j = 0; j < 4; ++j)
                #pragma unroll
                for (int q = 0; q < 4; ++q) c[mt][j][q] = 0.f;

        #pragma unroll
        for (int ks = 0; ks < 4; ++ks) {
            int kk = ks * 16;
            uint32_t ah[2][4], bh[2][4];
            #pragma unroll
            for (int mt = 0; mt < 2; ++mt)
                ldsm_x4(ah[mt], aOffH + ((16 * mt * PA1 + kk) << 1));
            #pragma unroll
            for (int pp = 0; pp < 2; ++pp)
                ldsm_x4t(bh[pp], bOffH + ((kk * PW1) << 1) + pp * 32);
            #pragma unroll
            for (int mt = 0; mt < 2; ++mt)
                #pragma unroll
                for (int j = 0; j < 4; ++j) {
                    int pp = j >> 1, w = j & 1;
                    mma_f16(c[mt][j], ah[mt], bh[pp][2 * w], bh[pp][2 * w + 1]);
                }
        }

        int M = rend - (gbase + s * GE1);
        if (M > GE1) M = GE1;
        #pragma unroll
        for (int mt = 0; mt < 2; ++mt) {
            int rowA = 16 * mt + (lane >> 2);
            int myrow = evenp ? rowA : rowA + 8;
            bool ok = myrow < M;
            float* bp = g_x1acc + (size_t)sdst[grp][s & 1][ok ? myrow : 0] * HID;
            #pragma unroll
            for (int j = 0; j < 4; ++j) {
                float sx = evenp ? c[mt][j][2] : c[mt][j][0];
                float sy = evenp ? c[mt][j][3] : c[mt][j][1];
                float rx = __shfl_xor_sync(0xffffffffu, sx, 1);
                float ry = __shfl_xor_sync(0xffffffffu, sy, 1);
                if (ok) {
                    if (evenp)
                        red4(bp + nbase + 8 * j + 2 * t,
                             c[mt][j][0], c[mt][j][1], rx, ry);
                    else
                        red4(bp + nbase + 8 * j + 2 * (t - 1),
                             rx, ry, c[mt][j][2], c[mt][j][3]);
                }
            }
        }
    }
}

// ---------------- LN1 + ReLU -> fp16 -----------------------------------------
__global__ void k_ln1(const float* __restrict__ g, const float* __restrict__ bb, int N) {
    int w = (blockIdx.x * blockDim.x + threadIdx.x) >> 5;
    int lane = threadIdx.x & 31;
    if (w >= N) return;
    float4 v = ((const float4*)(g_x1acc + (size_t)w * HID))[lane];
    float s = v.x + v.y + v.z + v.w;
    #pragma unroll
    for (int o = 16; o; o >>= 1) s += __shfl_xor_sync(0xffffffffu, s, o);
    float mu = s * (1.f / HID);
    float dx = v.x - mu, dy = v.y - mu, dz = v.z - mu, dw = v.w - mu;
    float q = dx * dx + dy * dy + dz * dz + dw * dw;
    #pragma unroll
    for (int o = 16; o; o >>= 1) q += __shfl_xor_sync(0xffffffffu, q, o);
    float inv = rsqrtf(q * (1.f / HID) + 1e-5f);
    float4 gv = ((const float4*)g)[lane];
    float4 bv = ((const float4*)bb)[lane];
    __half h[4];
    h[0] = __float2half(fmaxf(dx * inv * gv.x + bv.x, 0.f));
    h[1] = __float2half(fmaxf(dy * inv * gv.y + bv.y, 0.f));
    h[2] = __float2half(fmaxf(dz * inv * gv.z + bv.z, 0.f));
    h[3] = __float2half(fmaxf(dw * inv * gv.w + bv.w, 0.f));
    ((uint2*)(g_x1h + (size_t)w * HID))[lane] = *(uint2*)h;
}

// ---------------- layer-2: 512 edges/block, 2 groups x 32-edge sub-tiles -----
#define PA2 136
#define PW2 72
#define GE2 32
#define SM2_A    (128 * PW2)                 // W hi only
#define ABUF2    (GE2 * PA2)                 // single plane
#define SMEM2_BYTES ((SM2_A + 4 * ABUF2) * 2)

__global__ void __launch_bounds__(256) k_gemm2() {
    extern __shared__ __half sm[];
    __half* Wh = sm;
    __shared__ int sdst[2][2][GE2];

    int b = blockIdx.x;
    if (b >= g_tileoff[RNUM]) return;
    int tid = threadIdx.x;
    int r = 0;
    while (g_tileoff[r + 1] <= b) ++r;
    int base = g_off[r] + (b - g_tileoff[r]) * 512;
    int rend = g_off[r + 1];

    // stage W2[r] (commit bundled with first prefetch)
    {
        int row = tid >> 1, half = tid & 1;
        size_t src = ((size_t)r * HID + row) * DIN + half * 32;
        uint32_t dh = smem_u32(Wh + row * PW2 + half * 32);
        #pragma unroll
        for (int q = 0; q < 4; ++q)
            cpasync16(dh + q * 16, g_w2h + src + q * 8);
    }

    int grp = tid >> 7, gtid = tid & 127;
    int gbase = base + grp * 256;
    int nsub = (rend - gbase + 31) >> 5;
    if (nsub > 8) nsub = 8;
    if (nsub < 0) nsub = 0;

    int e = gtid >> 2, p = gtid & 3;
    auto prefetch = [&](int ss, int bb) {
        int gi = gbase + ss * GE2 + e;
        int row = 0;
        bool v = gi < rend;
        if (v) row = g_esrc2[gi];
        if (p == 0) sdst[grp][bb][e] = v ? g_edst[gi] : 0;
        const __half* sh = g_x1h + (size_t)row * HID + p * 32;
        uint32_t dh = smem_u32(sm + SM2_A + (grp * 2 + bb) * ABUF2 + e * PA2 + p * 32);
        #pragma unroll
        for (int q = 0; q < 4; ++q)
            cpasync16(dh + q * 16, sh + q * 8);
        cp_commit();
    };
    prefetch(0, 0);

    // block-wide barrier: W staged by all 256 threads, read by both groups
    cp_wait0();
    __syncthreads();

    int wid = gtid >> 5, lane = gtid & 31;
    int nbase = 16 * wid;
    uint32_t aBase = smem_u32(sm + SM2_A + grp * 2 * ABUF2) +
        (((lane & 15) * PA2 + 8 * (lane >> 4)) << 1);
    uint32_t bOffH = smem_u32(Wh) +
        (((((lane & 7) + 8 * ((lane >> 3) & 1)) * PW2) + nbase + 8 * (lane >> 4)) << 1);

    int barid = grp + 1;

    // hoist this warp's 16-col W slice to registers
    uint32_t wbh[8][4];
    #pragma unroll
    for (int ks = 0; ks < 8; ++ks)
        ldsm_x4t(wbh[ks], bOffH + ((ks * 16 * PW2) << 1));

    int t = lane & 3;
    bool evenp = (t & 1) == 0;

    for (int s = 0; s < nsub; ++s) {
        if (s > 0) { cp_wait0(); bar_sync(barid, 128); }
        if (s + 1 < nsub) prefetch(s + 1, (s + 1) & 1);

        uint32_t aOffH = aBase + ((s & 1) * ABUF2 << 1);

        float c[2][2][4];
        #pragma unroll
        for (int mt = 0; mt < 2; ++mt)
            #pragma unroll
            for (int j = 0; j < 2; ++j)
                #pragma unroll
                for (int q = 0; q < 4; ++q) c[mt][j][q] = 0.f;

        #pragma unroll
        for (int ks = 0; ks < 8; ++ks) {
            int kk = ks * 16;
            uint32_t ah[2][4];
            #pragma unroll
            for (int mt = 0; mt < 2; ++mt)
                ldsm_x4(ah[mt], aOffH + ((16 * mt * PA2 + kk) << 1));
            #pragma unroll
            for (int mt = 0; mt < 2; ++mt)
                #pragma unroll
                for (int j = 0; j < 2; ++j)
                    mma_f16(c[mt][j], ah[mt], wbh[ks][2 * j], wbh[ks][2 * j + 1]);
        }

        int M = rend - (gbase + s * GE2);
        if (M > GE2) M = GE2;
        #pragma unroll
        for (int mt = 0; mt < 2; ++mt) {
            int rowA = 16 * mt + (lane >> 2);
            int myrow = evenp ? rowA : rowA + 8;
            bool ok = myrow < M;
            float* bp = g_x2acc + (size_t)sdst[grp][s & 1][ok ? myrow : 0] * DIN;
            #pragma unroll
            for (int j = 0; j < 2; ++j) {
                float sx = evenp ? c[mt][j][2] : c[mt][j][0];
                float sy = evenp ? c[mt][j][3] : c[mt][j][1];
                float rx = __shfl_xor_sync(0xffffffffu, sx, 1);
                float ry = __shfl_xor_sync(0xffffffffu, sy, 1);
                if (ok) {
                    if (evenp)
                        red4(bp + nbase + 8 * j + 2 * t,
                             c[mt][j][0], c[mt][j][1], rx, ry);
                    else
                        red4(bp + nbase + 8 * j + 2 * (t - 1),
                             rx, ry, c[mt][j][2], c[mt][j][3]);
                }
            }
        }
    }
}

// ---------------- LN2 + residual ---------------------------------------------
__global__ void k_ln2res(const int* __restrict__ nid, const float* __restrict__ emb,
                         const float* __restrict__ g, const float* __restrict__ bb,
                         float* __restrict__ out, int N) {
    int w = (blockIdx.x * blockDim.x + threadIdx.x) >> 5;
    int lane = threadIdx.x & 31;
    if (w >= N) return;
    float2 v = ((const float2*)(g_x2acc + (size_t)w * DIN))[lane];
    float s = v.x + v.y;
    #pragma unroll
    for (int o = 16; o; o >>= 1) s += __shfl_xor_sync(0xffffffffu, s, o);
    float mu = s * (1.f / DIN);
    float dx = v.x - mu, dy = v.y - mu;
    float q = dx * dx + dy * dy;
    #pragma unroll
    for (int o = 16; o; o >>= 1) q += __shfl_xor_sync(0xffffffffu, q, o);
    float inv = rsqrtf(q * (1.f / DIN) + 1e-5f);
    float2 gv = ((const float2*)g)[lane];
    float2 bv = ((const float2*)bb)[lane];
    float2 xr = ((const float2*)(emb + (size_t)nid[w] * DIN))[lane];
    float2 o2;
    o2.x = dx * inv * gv.x + bv.x + xr.x;
    o2.y = dy * inv * gv.y + bv.y + xr.y;
    ((float2*)(out + (size_t)w * DIN))[lane] = o2;
}

// ---------------- launch -----------------------------------------------------
extern "C" void kernel_launch(void* const* d_in, const int* in_sizes, int n_in,
                              void* d_out, int out_size) {
    const int*   nid   = (const int*)d_in[0];
    const int*   eidx  = (const int*)d_in[1];
    const int*   etype = (const int*)d_in[2];
    const float* emb   = (const float*)d_in[3];
    const float* W1    = (const float*)d_in[4];
    const float* W2    = (const float*)d_in[5];
    const float* ln1g  = (const float*)d_in[6];
    const float* ln1b  = (const float*)d_in[7];
    const float* ln2g  = (const float*)d_in[8];
    const float* ln2b  = (const float*)d_in[9];
    float* out = (float*)d_out;

    int N = in_sizes[0];
    int E = in_sizes[2];

    cudaFuncSetAttribute(k_gemm1, cudaFuncAttributeMaxDynamicSharedMemorySize, SMEM1_BYTES);
    cudaFuncSetAttribute(k_gemm2, cudaFuncAttributeMaxDynamicSharedMemorySize, SMEM2_BYTES);

    int blocks = (E + 511) / 512 + RNUM;

    k_prep<<<1024, 256>>>(emb, W1, W2, etype, N, E);
    k_scan<<<1, 32>>>();
    k_bucket<<<(E + 255) / 256, 256>>>(etype, eidx, nid, E);
    k_gemm1<<<blocks, 256, SMEM1_BYTES>>>();
    k_ln1<<<(N * 32 + 255) / 256, 256>>>(ln1g, ln1b, N);
    k_gemm2<<<blocks, 256, SMEM2_BYTES>>>();
    k_ln2res<<<(N * 32 + 255) / 256, 256>>>(nid, emb, ln2g, ln2b, out, N);
}

// round 17
// speedup vs baseline: 1.8755x; 1.0168x over previous
#include <cuda_runtime.h>
#include <cuda_fp16.h>
#include <cstdint>

#define MAXN 50000
#define MAXE 600000
#define RNUM 16
#define DIN  64
#define HID  128

// ---------------- scratch ----------------------------------------------------
__device__ float g_x1acc[(size_t)MAXN * HID];
__device__ float g_x2acc[(size_t)MAXN * DIN];
__device__ __half g_embh[(size_t)MAXN * DIN];
__device__ __half g_x1h[(size_t)MAXN * HID];
__device__ __half g_w1h[RNUM * DIN * HID];
__device__ __half g_w2h[RNUM * HID * DIN];
__device__ int g_esrc1[MAXE];
__device__ int g_esrc2[MAXE];
__device__ int g_edst[MAXE];
__device__ int g_cnt[RNUM];          // zero at load; k_scan consumes AND resets
__device__ int g_off[RNUM + 1];
__device__ int g_cursor[RNUM];
__device__ int g_tileoff[RNUM + 1];

// ---------------- PTX helpers ------------------------------------------------
__device__ __forceinline__ uint32_t smem_u32(const void* p) {
    return (uint32_t)__cvta_generic_to_shared(p);
}
__device__ __forceinline__ void ldsm_x4(uint32_t* r, uint32_t a) {
    asm volatile("ldmatrix.sync.aligned.m8n8.x4.shared.b16 {%0,%1,%2,%3}, [%4];\n"
                 : "=r"(r[0]), "=r"(r[1]), "=r"(r[2]), "=r"(r[3]) : "r"(a));
}
__device__ __forceinline__ void ldsm_x4t(uint32_t* r, uint32_t a) {
    asm volatile("ldmatrix.sync.aligned.m8n8.x4.trans.shared.b16 {%0,%1,%2,%3}, [%4];\n"
                 : "=r"(r[0]), "=r"(r[1]), "=r"(r[2]), "=r"(r[3]) : "r"(a));
}
__device__ __forceinline__ void mma_f16(float* c, const uint32_t* a, uint32_t b0, uint32_t b1) {
    asm volatile("mma.sync.aligned.m16n8k16.row.col.f32.f16.f16.f32 "
                 "{%0,%1,%2,%3},{%4,%5,%6,%7},{%8,%9},{%0,%1,%2,%3};\n"
                 : "+f"(c[0]), "+f"(c[1]), "+f"(c[2]), "+f"(c[3])
                 : "r"(a[0]), "r"(a[1]), "r"(a[2]), "r"(a[3]), "r"(b0), "r"(b1));
}
__device__ __forceinline__ void cpasync16(uint32_t saddr, const void* g) {
    asm volatile("cp.async.cg.shared.global [%0], [%1], 16;\n" :: "r"(saddr), "l"(g));
}
__device__ __forceinline__ void cp_commit() {
    asm volatile("cp.async.commit_group;\n");
}
__device__ __forceinline__ void cp_wait0() {
    asm volatile("cp.async.wait_group 0;\n");
}
__device__ __forceinline__ void cp_wait1() {
    asm volatile("cp.async.wait_group 1;\n");
}
__device__ __forceinline__ void bar_sync(int id, int n) {
    asm volatile("bar.sync %0, %1;\n" :: "r"(id), "r"(n) : "memory");
}
__device__ __forceinline__ void red4(float* p, float x, float y, float z, float w) {
    asm volatile("red.global.add.v4.f32 [%0], {%1,%2,%3,%4};\n"
                 :: "l"(p), "f"(x), "f"(y), "f"(z), "f"(w) : "memory");
}

// ---------------- prep: zero + convert + relation hist (fused) ---------------
__global__ void k_prep(const float* __restrict__ emb, const float* __restrict__ W1,
                       const float* __restrict__ W2, const int* __restrict__ et,
                       int N, int E) {
    __shared__ int s[RNUM];
    if (threadIdx.x < RNUM) s[threadIdx.x] = 0;
    __syncthreads();
    int stride = gridDim.x * blockDim.x;
    int i = blockIdx.x * blockDim.x + threadIdx.x;
    float4 z = make_float4(0.f, 0.f, 0.f, 0.f);
    int n1 = N * (HID / 4);
    for (int k = i; k < n1; k += stride) ((float4*)g_x1acc)[k] = z;
    int n2 = N * (DIN / 4);
    for (int k = i; k < n2; k += stride) ((float4*)g_x2acc)[k] = z;
    int ne = N * DIN;
    for (int k = i; k < ne; k += stride) g_embh[k] = __float2half(emb[k]);
    for (int k = i; k < RNUM * DIN * HID; k += stride) g_w1h[k] = __float2half(W1[k]);
    for (int k = i; k < RNUM * HID * DIN; k += stride) g_w2h[k] = __float2half(W2[k]);
    for (int k = i; k < E; k += stride) atomicAdd(&s[et[k]], 1);
    __syncthreads();
    if (threadIdx.x < RNUM && s[threadIdx.x]) atomicAdd(&g_cnt[threadIdx.x], s[threadIdx.x]);
}

// ---------------- scan (consume + reset g_cnt) --------------------------------
__global__ void k_scan() {
    if (threadIdx.x == 0 && blockIdx.x == 0) {
        int o = 0, t = 0;
        for (int r = 0; r < RNUM; ++r) {
            g_off[r] = o; g_cursor[r] = o; g_tileoff[r] = t;
            o += g_cnt[r];
            t += (g_cnt[r] + 511) >> 9;        // 512-edge blocks
            g_cnt[r] = 0;
        }
        g_off[RNUM] = o; g_tileoff[RNUM] = t;
    }
}
__global__ void k_bucket(const int* __restrict__ et, const int* __restrict__ eidx,
                         const int* __restrict__ nid, int E) {
    __shared__ int lcnt[RNUM], lbase[RNUM];
    int e = blockIdx.x * 256 + threadIdx.x;
    if (threadIdx.x < RNUM) lcnt[threadIdx.x] = 0;
    __syncthreads();
    int r = 0, rank = 0, s = 0, d = 0;
    if (e < E) {
        r = et[e]; s = eidx[e]; d = eidx[E + e];
        rank = atomicAdd(&lcnt[r], 1);
    }
    __syncthreads();
    if (threadIdx.x < RNUM && lcnt[threadIdx.x])
        lbase[threadIdx.x] = atomicAdd(&g_cursor[threadIdx.x], lcnt[threadIdx.x]);
    __syncthreads();
    if (e < E) {
        int pos = lbase[r] + rank;
        g_esrc1[pos] = nid[s];
        g_esrc2[pos] = s;
        g_edst[pos]  = d;
    }
}

// ---------------- layer-1: 512 edges/block, 2 groups, 3-stage pipeline -------
#define PA1 72
#define PW1 136
#define GE1 32
#define SM1_A    (64 * PW1)                  // W
#define ABUF1    (GE1 * PA1)                 // per 32-edge buffer (single plane)
#define SMEM1_BYTES ((SM1_A + 6 * ABUF1) * 2)

__global__ void __launch_bounds__(256) k_gemm1() {
    extern __shared__ __half sm[];
    __half* Wh = sm;
    __shared__ int sdst[2][3][GE1];

    int b = blockIdx.x;
    if (b >= g_tileoff[RNUM]) return;
    int tid = threadIdx.x;
    int r = 0;
    while (g_tileoff[r + 1] <= b) ++r;
    int base = g_off[r] + (b - g_tileoff[r]) * 512;
    int rend = g_off[r + 1];

    // stage W1[r] (commit bundled with prefetch(0))
    {
        int row = tid >> 2, seg = tid & 3;
        size_t src = ((size_t)r * DIN + row) * HID + seg * 32;
        uint32_t dh = smem_u32(Wh + row * PW1 + seg * 32);
        #pragma unroll
        for (int q = 0; q < 4; ++q)
            cpasync16(dh + q * 16, g_w1h + src + q * 8);
    }

    int grp = tid >> 7, gtid = tid & 127;
    int gbase = base + grp * 256;
    int nsub = (rend - gbase + 31) >> 5;
    if (nsub > 8) nsub = 8;
    if (nsub < 0) nsub = 0;

    int e = gtid >> 2, p = gtid & 3;
    auto prefetch = [&](int ss, int bb) {
        int gi = gbase + ss * GE1 + e;
        int row = 0;
        bool v = gi < rend;
        if (v) row = g_esrc1[gi];
        if (p == 0) sdst[grp][bb][e] = v ? g_edst[gi] : 0;
        const __half* sh = g_embh + (size_t)row * DIN + p * 16;
        uint32_t dh = smem_u32(sm + SM1_A + (grp * 3 + bb) * ABUF1 + e * PA1 + p * 16);
        cpasync16(dh, sh); cpasync16(dh + 16, sh + 8);
        cp_commit();
    };
    prefetch(0, 0);                     // commits W + A0
    if (nsub > 1) { prefetch(1, 1); cp_wait1(); } else cp_wait0();
    __syncthreads();                    // W visible to both groups

    int wid = gtid >> 5, lane = gtid & 31;
    int nbase = 32 * wid;
    uint32_t aBase = smem_u32(sm + SM1_A + grp * 3 * ABUF1) +
        (((lane & 15) * PA1 + 8 * (lane >> 4)) << 1);
    uint32_t bOffH = smem_u32(Wh) +
        (((((lane & 7) + 8 * ((lane >> 3) & 1)) * PW1) + nbase + 8 * (lane >> 4)) << 1);

    int t = lane & 3;
    bool evenp = (t & 1) == 0;
    int barid = grp + 1;

    for (int s = 0; s < nsub; ++s) {
        if (s > 0) {
            if (s + 1 < nsub) cp_wait1(); else cp_wait0();
            bar_sync(barid, 128);
        }
        if (s + 2 < nsub) prefetch(s + 2, (s + 2) % 3);

        int buf = s % 3;
        uint32_t aOffH = aBase + ((buf * ABUF1) << 1);

        float c[2][4][4];
        #pragma unroll
        for (int mt = 0; mt < 2; ++mt)
            #pragma unroll
            for (int j = 0; j < 4; ++j)
                #pragma unroll
                for (int q = 0; q < 4; ++q) c[mt][j][q] = 0.f;

        #pragma unroll
        for (int ks = 0; ks < 4; ++ks) {
            int kk = ks * 16;
            uint32_t ah[2][4], bh[2][4];
            #pragma unroll
            for (int mt = 0; mt < 2; ++mt)
                ldsm_x4(ah[mt], aOffH + ((16 * mt * PA1 + kk) << 1));
            #pragma unroll
            for (int pp = 0; pp < 2; ++pp)
                ldsm_x4t(bh[pp], bOffH + ((kk * PW1) << 1) + pp * 32);
            #pragma unroll
            for (int mt = 0; mt < 2; ++mt)
                #pragma unroll
                for (int j = 0; j < 4; ++j) {
                    int pp = j >> 1, w = j & 1;
                    mma_f16(c[mt][j], ah[mt], bh[pp][2 * w], bh[pp][2 * w + 1]);
                }
        }

        int M = rend - (gbase + s * GE1);
        if (M > GE1) M = GE1;
        #pragma unroll
        for (int mt = 0; mt < 2; ++mt) {
            int rowA = 16 * mt + (lane >> 2);
            int myrow = evenp ? rowA : rowA + 8;
            bool ok = myrow < M;
            float* bp = g_x1acc + (size_t)sdst[grp][buf][ok ? myrow : 0] * HID;
            #pragma unroll
            for (int j = 0; j < 4; ++j) {
                float sx = evenp ? c[mt][j][2] : c[mt][j][0];
                float sy = evenp ? c[mt][j][3] : c[mt][j][1];
                float rx = __shfl_xor_sync(0xffffffffu, sx, 1);
                float ry = __shfl_xor_sync(0xffffffffu, sy, 1);
                if (ok) {
                    if (evenp)
                        red4(bp + nbase + 8 * j + 2 * t,
                             c[mt][j][0], c[mt][j][1], rx, ry);
                    else
                        red4(bp + nbase + 8 * j + 2 * (t - 1),
                             rx, ry, c[mt][j][2], c[mt][j][3]);
                }
            }
        }
    }
}

// ---------------- LN1 + ReLU -> fp16 -----------------------------------------
__global__ void k_ln1(const float* __restrict__ g, const float* __restrict__ bb, int N) {
    int w = (blockIdx.x * blockDim.x + threadIdx.x) >> 5;
    int lane = threadIdx.x & 31;
    if (w >= N) return;
    float4 v = ((const float4*)(g_x1acc + (size_t)w * HID))[lane];
    float s = v.x + v.y + v.z + v.w;
    #pragma unroll
    for (int o = 16; o; o >>= 1) s += __shfl_xor_sync(0xffffffffu, s, o);
    float mu = s * (1.f / HID);
    float dx = v.x - mu, dy = v.y - mu, dz = v.z - mu, dw = v.w - mu;
    float q = dx * dx + dy * dy + dz * dz + dw * dw;
    #pragma unroll
    for (int o = 16; o; o >>= 1) q += __shfl_xor_sync(0xffffffffu, q, o);
    float inv = rsqrtf(q * (1.f / HID) + 1e-5f);
    float4 gv = ((const float4*)g)[lane];
    float4 bv = ((const float4*)bb)[lane];
    __half h[4];
    h[0] = __float2half(fmaxf(dx * inv * gv.x + bv.x, 0.f));
    h[1] = __float2half(fmaxf(dy * inv * gv.y + bv.y, 0.f));
    h[2] = __float2half(fmaxf(dz * inv * gv.z + bv.z, 0.f));
    h[3] = __float2half(fmaxf(dw * inv * gv.w + bv.w, 0.f));
    ((uint2*)(g_x1h + (size_t)w * HID))[lane] = *(uint2*)h;
}

// ---------------- layer-2: 512 edges/block, 2 groups, 3-stage pipeline -------
#define PA2 136
#define PW2 72
#define GE2 32
#define SM2_A    (128 * PW2)                 // W
#define ABUF2    (GE2 * PA2)
#define SMEM2_BYTES ((SM2_A + 6 * ABUF2) * 2)

__global__ void __launch_bounds__(256) k_gemm2() {
    extern __shared__ __half sm[];
    __half* Wh = sm;
    __shared__ int sdst[2][3][GE2];

    int b = blockIdx.x;
    if (b >= g_tileoff[RNUM]) return;
    int tid = threadIdx.x;
    int r = 0;
    while (g_tileoff[r + 1] <= b) ++r;
    int base = g_off[r] + (b - g_tileoff[r]) * 512;
    int rend = g_off[r + 1];

    // stage W2[r] (commit bundled with prefetch(0))
    {
        int row = tid >> 1, half = tid & 1;
        size_t src = ((size_t)r * HID + row) * DIN + half * 32;
        uint32_t dh = smem_u32(Wh + row * PW2 + half * 32);
        #pragma unroll
        for (int q = 0; q < 4; ++q)
            cpasync16(dh + q * 16, g_w2h + src + q * 8);
    }

    int grp = tid >> 7, gtid = tid & 127;
    int gbase = base + grp * 256;
    int nsub = (rend - gbase + 31) >> 5;
    if (nsub > 8) nsub = 8;
    if (nsub < 0) nsub = 0;

    int e = gtid >> 2, p = gtid & 3;
    auto prefetch = [&](int ss, int bb) {
        int gi = gbase + ss * GE2 + e;
        int row = 0;
        bool v = gi < rend;
        if (v) row = g_esrc2[gi];
        if (p == 0) sdst[grp][bb][e] = v ? g_edst[gi] : 0;
        const __half* sh = g_x1h + (size_t)row * HID + p * 32;
        uint32_t dh = smem_u32(sm + SM2_A + (grp * 3 + bb) * ABUF2 + e * PA2 + p * 32);
        #pragma unroll
        for (int q = 0; q < 4; ++q)
            cpasync16(dh + q * 16, sh + q * 8);
        cp_commit();
    };
    prefetch(0, 0);
    if (nsub > 1) { prefetch(1, 1); cp_wait1(); } else cp_wait0();
    __syncthreads();                    // W visible to both groups

    int wid = gtid >> 5, lane = gtid & 31;
    int nbase = 16 * wid;
    uint32_t aBase = smem_u32(sm + SM2_A + grp * 3 * ABUF2) +
        (((lane & 15) * PA2 + 8 * (lane >> 4)) << 1);
    uint32_t bOffH = smem_u32(Wh) +
        (((((lane & 7) + 8 * ((lane >> 3) & 1)) * PW2) + nbase + 8 * (lane >> 4)) << 1);

    int barid = grp + 1;

    // hoist this warp's 16-col W slice to registers
    uint32_t wbh[8][4];
    #pragma unroll
    for (int ks = 0; ks < 8; ++ks)
        ldsm_x4t(wbh[ks], bOffH + ((ks * 16 * PW2) << 1));

    int t = lane & 3;
    bool evenp = (t & 1) == 0;

    for (int s = 0; s < nsub; ++s) {
        if (s > 0) {
            if (s + 1 < nsub) cp_wait1(); else cp_wait0();
            bar_sync(barid, 128);
        }
        if (s + 2 < nsub) prefetch(s + 2, (s + 2) % 3);

        int buf = s % 3;
        uint32_t aOffH = aBase + ((buf * ABUF2) << 1);

        float c[2][2][4];
        #pragma unroll
        for (int mt = 0; mt < 2; ++mt)
            #pragma unroll
            for (int j = 0; j < 2; ++j)
                #pragma unroll
                for (int q = 0; q < 4; ++q) c[mt][j][q] = 0.f;

        #pragma unroll
        for (int ks = 0; ks < 8; ++ks) {
            int kk = ks * 16;
            uint32_t ah[2][4];
            #pragma unroll
            for (int mt = 0; mt < 2; ++mt)
                ldsm_x4(ah[mt], aOffH + ((16 * mt * PA2 + kk) << 1));
            #pragma unroll
            for (int mt = 0; mt < 2; ++mt)
                #pragma unroll
                for (int j = 0; j < 2; ++j)
                    mma_f16(c[mt][j], ah[mt], wbh[ks][2 * j], wbh[ks][2 * j + 1]);
        }

        int M = rend - (gbase + s * GE2);
        if (M > GE2) M = GE2;
        #pragma unroll
        for (int mt = 0; mt < 2; ++mt) {
            int rowA = 16 * mt + (lane >> 2);
            int myrow = evenp ? rowA : rowA + 8;
            bool ok = myrow < M;
            float* bp = g_x2acc + (size_t)sdst[grp][buf][ok ? myrow : 0] * DIN;
            #pragma unroll
            for (int j = 0; j < 2; ++j) {
                float sx = evenp ? c[mt][j][2] : c[mt][j][0];
                float sy = evenp ? c[mt][j][3] : c[mt][j][1];
                float rx = __shfl_xor_sync(0xffffffffu, sx, 1);
                float ry = __shfl_xor_sync(0xffffffffu, sy, 1);
                if (ok) {
                    if (evenp)
                        red4(bp + nbase + 8 * j + 2 * t,
                             c[mt][j][0], c[mt][j][1], rx, ry);
                    else
                        red4(bp + nbase + 8 * j + 2 * (t - 1),
                             rx, ry, c[mt][j][2], c[mt][j][3]);
                }
            }
        }
    }
}

// ---------------- LN2 + residual ---------------------------------------------
__global__ void k_ln2res(const int* __restrict__ nid, const float* __restrict__ emb,
                         const float* __restrict__ g, const float* __restrict__ bb,
                         float* __restrict__ out, int N) {
    int w = (blockIdx.x * blockDim.x + threadIdx.x) >> 5;
    int lane = threadIdx.x & 31;
    if (w >= N) return;
    float2 v = ((const float2*)(g_x2acc + (size_t)w * DIN))[lane];
    float s = v.x + v.y;
    #pragma unroll
    for (int o = 16; o; o >>= 1) s += __shfl_xor_sync(0xffffffffu, s, o);
    float mu = s * (1.f / DIN);
    float dx = v.x - mu, dy = v.y - mu;
    float q = dx * dx + dy * dy;
    #pragma unroll
    for (int o = 16; o; o >>= 1) q += __shfl_xor_sync(0xffffffffu, q, o);
    float inv = rsqrtf(q * (1.f / DIN) + 1e-5f);
    float2 gv = ((const float2*)g)[lane];
    float2 bv = ((const float2*)bb)[lane];
    float2 xr = ((const float2*)(emb + (size_t)nid[w] * DIN))[lane];
    float2 o2;
    o2.x = dx * inv * gv.x + bv.x + xr.x;
    o2.y = dy * inv * gv.y + bv.y + xr.y;
    ((float2*)(out + (size_t)w * DIN))[lane] = o2;
}

// ---------------- launch -----------------------------------------------------
extern "C" void kernel_launch(void* const* d_in, const int* in_sizes, int n_in,
                              void* d_out, int out_size) {
    const int*   nid   = (const int*)d_in[0];
    const int*   eidx  = (const int*)d_in[1];
    const int*   etype = (const int*)d_in[2];
    const float* emb   = (const float*)d_in[3];
    const float* W1    = (const float*)d_in[4];
    const float* W2    = (const float*)d_in[5];
    const float* ln1g  = (const float*)d_in[6];
    const float* ln1b  = (const float*)d_in[7];
    const float* ln2g  = (const float*)d_in[8];
    const float* ln2b  = (const float*)d_in[9];
    float* out = (float*)d_out;

    int N = in_sizes[0];
    int E = in_sizes[2];

    cudaFuncSetAttribute(k_gemm1, cudaFuncAttributeMaxDynamicSharedMemorySize, SMEM1_BYTES);
    cudaFuncSetAttribute(k_gemm2, cudaFuncAttributeMaxDynamicSharedMemorySize, SMEM2_BYTES);

    int blocks = (E + 511) / 512 + RNUM;

    k_prep<<<1024, 256>>>(emb, W1, W2, etype, N, E);
    k_scan<<<1, 32>>>();
    k_bucket<<<(E + 255) / 256, 256>>>(etype, eidx, nid, E);
    k_gemm1<<<blocks, 256, SMEM1_BYTES>>>();
    k_ln1<<<(N * 32 + 255) / 256, 256>>>(ln1g, ln1b, N);
    k_gemm2<<<blocks, 256, SMEM2_BYTES>>>();
    k_ln2res<<<(N * 32 + 255) / 256, 256>>>(nid, emb, ln2g, ln2b, out, N);
}